// round 5
// baseline (speedup 1.0000x reference)
#include <cuda_runtime.h>
#include <cstdint>
#include <cstddef>

// Problem constants
#define BT    4
#define NN    2048
#define FIN   512
#define FOUT  128
#define PIN   256
#define POUT  128
#define HEAD  4
#define KD    32           // per-head dim

typedef unsigned long long u64;

// Scratch (device globals; no allocation allowed)
__device__ float g_x   [2*BT*NN*POUT];   // init linear output (residual source)
__device__ float g_xh  [2*BT*NN*POUT];   // proj output (per-head features)
__device__ float g_G   [2*BT*NN*POUT];   // PPIGE output
__device__ float g_pqs4[2*BT*NN*16];     // per row i, head h: {-s1, e^{s1}, e^{.2 s1}, 0}
__device__ float g_tuv4[2*BT*NN*16];     // per col j, head h: {t, e^{t}, e^{.2 t}, 0}
__device__ float g_hgge[2*BT*FOUT];

// f32x2 packed math
#define PACK2(d, lo, hi) asm("mov.b64 %0, {%1, %2};" : "=l"(d) : "r"(lo), "r"(hi))
#define UNPACK2(lo, hi, s) asm("mov.b64 {%0, %1}, %2;" : "=r"(lo), "=r"(hi) : "l"(s))
#define FMA2(d, a, b) asm("fma.rn.f32x2 %0, %1, %2, %0;" : "+l"(d) : "l"(a), "l"(b))
#define ADD2(d, a)    asm("add.rn.f32x2 %0, %1, %0;" : "+l"(d) : "l"(a))

// ---------------------------------------------------------------------------
// C[r][c] = sum_k A[r][k]*W[c][k] (+bias).  BM=64, 128 cols, BK=16.
// mode 0: A = bio_{a,b}, C = g_x.
// mode 1: A = g_x, C = g_xh, fused epilogue computes attention scalars.
// ---------------------------------------------------------------------------
__global__ __launch_bounds__(256) void gemm_tn(
    const float* __restrict__ A0, const float* __restrict__ A1,
    const float* __restrict__ W,  const float* __restrict__ bias,
    const float* __restrict__ attw, const float* __restrict__ attb,
    int Kdim, int mode)
{
    __shared__ float As[16][65];
    __shared__ float Ws[16][128];

    const int branch = blockIdx.y;
    const float* Ain;
    float* Cout;
    if (mode == 0) { Ain = branch ? A1 : A0;                   Cout = g_x;  }
    else           { Ain = g_x + (size_t)branch * BT*NN*POUT;  Cout = g_xh; }
    Cout += (size_t)branch * BT*NN*POUT;

    const int row0 = blockIdx.x * 64;
    const int tid  = threadIdx.x;
    const int tx   = tid & 31;      // lane: col group (4 cols)
    const int ty   = tid >> 5;      // warp: row group (8 rows)

    float acc[8][4];
#pragma unroll
    for (int i = 0; i < 8; i++)
#pragma unroll
        for (int j = 0; j < 4; j++) acc[i][j] = 0.f;

    for (int k0 = 0; k0 < Kdim; k0 += 16) {
        {   // A tile: 64x16
            int r = tid >> 2, kq = tid & 3;
            float4 v = *(const float4*)&Ain[(size_t)(row0 + r)*Kdim + k0 + kq*4];
            As[kq*4+0][r] = v.x; As[kq*4+1][r] = v.y;
            As[kq*4+2][r] = v.z; As[kq*4+3][r] = v.w;
        }
        {   // W tile: 128x16
            int c = tid >> 1, kh = tid & 1;
#pragma unroll
            for (int p = 0; p < 2; p++) {
                int kk = kh*8 + p*4;
                float4 v = *(const float4*)&W[(size_t)c*Kdim + k0 + kk];
                Ws[kk+0][c] = v.x; Ws[kk+1][c] = v.y;
                Ws[kk+2][c] = v.z; Ws[kk+3][c] = v.w;
            }
        }
        __syncthreads();
#pragma unroll
        for (int k = 0; k < 16; k++) {
            float4 wv = *(const float4*)&Ws[k][tx*4];
            float av[8];
#pragma unroll
            for (int i = 0; i < 8; i++) av[i] = As[k][ty*8 + i];
#pragma unroll
            for (int i = 0; i < 8; i++) {
                acc[i][0] += av[i]*wv.x; acc[i][1] += av[i]*wv.y;
                acc[i][2] += av[i]*wv.z; acc[i][3] += av[i]*wv.w;
            }
        }
        __syncthreads();
    }
    float4 bv = make_float4(0.f, 0.f, 0.f, 0.f);
    if (bias) bv = *(const float4*)&bias[tx*4];
#pragma unroll
    for (int i = 0; i < 8; i++) {
        float4 o = make_float4(acc[i][0]+bv.x, acc[i][1]+bv.y,
                               acc[i][2]+bv.z, acc[i][3]+bv.w);
        *(float4*)&Cout[(size_t)(row0 + ty*8 + i)*POUT + tx*4] = o;
    }

    if (mode == 1) {
        // Fused attention-scalar epilogue. cols owned by this lane all lie in
        // head h = tx>>3; local col = (tx&7)*4 + q.
        const int h = tx >> 3, lq = tx & 7;
        float w1[4], w2[4];
#pragma unroll
        for (int q = 0; q < 4; q++) {
            w1[q] = attw[h*2*KD + lq*4 + q];
            w2[q] = attw[h*2*KD + KD + lq*4 + q];
        }
        const float bb = attb[h];
#pragma unroll
        for (int i = 0; i < 8; i++) {
            float p1 = acc[i][0]*w1[0] + acc[i][1]*w1[1]
                     + acc[i][2]*w1[2] + acc[i][3]*w1[3];
            float p2 = acc[i][0]*w2[0] + acc[i][1]*w2[1]
                     + acc[i][2]*w2[2] + acc[i][3]*w2[3];
#pragma unroll
            for (int off = 1; off < 8; off <<= 1) {
                p1 += __shfl_xor_sync(0xffffffffu, p1, off);
                p2 += __shfl_xor_sync(0xffffffffu, p2, off);
            }
            if (lq == 0) {
                size_t r = (size_t)branch*BT*NN + row0 + ty*8 + i;
                float s1 = p1, t = p2 + bb;
                float* pq = &g_pqs4[r*16 + h*4];
                pq[0] = -s1;
                pq[1] = __expf(s1);
                pq[2] = __expf(0.2f*s1);
                float* tv = &g_tuv4[r*16 + h*4];
                tv[0] = t;
                tv[1] = __expf(t);
                tv[2] = __expf(0.2f*t);
            }
        }
    }
}

// ---------------------------------------------------------------------------
// GGE
// ---------------------------------------------------------------------------
__global__ __launch_bounds__(512) void gge_kernel(
    const float* __restrict__ a, const float* __restrict__ b,
    const float* __restrict__ W1, const float* __restrict__ b1,
    const float* __restrict__ W2, const float* __restrict__ b2)
{
    __shared__ float in_s[FIN];
    __shared__ float h1[128];
    const int bi = blockIdx.x, branch = blockIdx.y;
    const float* in = (branch ? b : a) + bi*FIN;
    const int tid = threadIdx.x, warp = tid >> 5, lane = tid & 31;
    if (tid < FIN) in_s[tid] = in[tid];
    __syncthreads();
    for (int o = warp; o < 128; o += 16) {
        float acc = 0.f;
        for (int k = lane; k < FIN; k += 32) acc += in_s[k] * W1[(size_t)o*FIN + k];
#pragma unroll
        for (int off = 16; off; off >>= 1) acc += __shfl_xor_sync(0xffffffffu, acc, off);
        if (lane == 0) h1[o] = fmaxf(acc + b1[o], 0.f);
    }
    __syncthreads();
    for (int o = warp; o < 128; o += 16) {
        float acc = 0.f;
        for (int k = lane; k < 128; k += 32) acc += h1[k] * W2[o*128 + k];
#pragma unroll
        for (int off = 16; off; off >>= 1) acc += __shfl_xor_sync(0xffffffffu, acc, off);
        if (lane == 0) g_hgge[(branch*BT + bi)*FOUT + o] = fmaxf(acc + b2[o], 0.f);
    }
}

// ---------------------------------------------------------------------------
// Dense register-tiled attention GEMM: out = relu( (w @ xh) / rowsum(w) ) + x
// CTA: 128 i-rows x 128 cols (all heads), loop over j in tiles of 32.
// Thread (ti=tid>>4, tk=tid&15): 8 i x 8 k, head = tk>>2.
// f32x2 packed accumulation: acc pairs over (i_even, i_odd).
// ---------------------------------------------------------------------------
#define TJ 32
#define W_PS 4226                  // per-head plane stride (32*132 + 2) floats
#define W_JS 132                   // per-j stride within plane
#define XH_OFF (4*W_PS)            // 16904
#define PQ_OFF (XH_OFF + TJ*128)   // +4096
#define TUV_OFF (PQ_OFF + 128*20)  // +2560
#define AM_OFF (TUV_OFF + TJ*16)   // +512
#define SM_FLOATS (AM_OFF + 128)
#define SM_BYTES (SM_FLOATS*4)

__global__ __launch_bounds__(256) void attn_dense(
    const int* __restrict__ A0, const int* __restrict__ A1)
{
    extern __shared__ float sm[];
    float* w_s   = sm;
    float* xh_s  = sm + XH_OFF;
    float* pq_s  = sm + PQ_OFF;
    float* tuv_s = sm + TUV_OFF;
    unsigned* am_s = (unsigned*)(sm + AM_OFF);

    const int branch = blockIdx.z, b = blockIdx.y;
    const int i0 = blockIdx.x * 128;
    const int tid = threadIdx.x, warp = tid >> 5, lane = tid & 31;
    const int tk = tid & 15, ti = tid >> 4;
    const int h = tk >> 2, k0 = tk * 8, it8 = ti * 8;

    const size_t rbase = (size_t)(branch*BT + b) * NN;
    const float* xhb = g_xh + rbase * POUT;
    const float* tvb = g_tuv4 + rbase * 16;
    const int* Abase = (branch ? A1 : A0) + ((size_t)b*NN + i0) * NN;

    // stage pq (once): 128 rows x 4 heads x float4, padded stride 20
    {
        const float* src = g_pqs4 + (rbase + i0) * 16;
#pragma unroll
        for (int p = 0; p < 2; p++) {
            int idx = tid + p*256;          // 512 float4
            int i = idx >> 2, c = idx & 3;
            float4 v = *(const float4*)&src[i*16 + c*4];
            *(float4*)&pq_s[i*20 + c*4] = v;
        }
    }

    u64 accp[4][8];
    u64 denp[4];
#pragma unroll
    for (int ip = 0; ip < 4; ip++) {
        denp[ip] = 0ull;
#pragma unroll
        for (int k = 0; k < 8; k++) accp[ip][k] = 0ull;
    }

    const float* wrd = w_s + h*W_PS + it8;

    for (int jt = 0; jt < NN; jt += TJ) {
        __syncthreads();
        // phase 1: adjacency masks (ballot) + tuv
        {
#pragma unroll
            for (int pass = 0; pass < 4; pass++) {
                const int* Ar = Abase + (size_t)(pass*32 + warp*4)*NN + jt + lane;
                int vals[4];
#pragma unroll
                for (int r = 0; r < 4; r++) vals[r] = Ar[(size_t)r*NN];
#pragma unroll
                for (int r = 0; r < 4; r++) {
                    unsigned m = __ballot_sync(0xffffffffu, vals[r] != 0);
                    if (lane == 0) am_s[pass*32 + warp*4 + r] = m;
                }
            }
        }
        if (tid < 128) {    // tuv: 32 j x 4 float4
            int j = tid >> 2, c = tid & 3;
            float4 v = *(const float4*)&tvb[(size_t)(jt + j)*16 + c*4];
            *(float4*)&tuv_s[j*16 + c*4] = v;
        }
        __syncthreads();
        // phase 2: w field + xh tile
        {
            // xh: 32 x 128 floats = 1024 float4
#pragma unroll
            for (int p = 0; p < 4; p++) {
                int idx = tid + p*256;
                int j = idx >> 5, c = idx & 31;
                float4 v = *(const float4*)&xhb[(size_t)(jt + j)*POUT + c*4];
                *(float4*)&xh_s[j*128 + c*4] = v;
            }
            // w: 16 tuples per warp; tuple = (ib,hh,jg), lanes over i
#pragma unroll
            for (int rr = 0; rr < 16; rr++) {
                int tup = rr*8 + warp;
                int ib = tup >> 5, hh = (tup >> 3) & 3, jg = tup & 7;
                int i = ib*32 + lane;
                float4 pq = *(const float4*)&pq_s[i*20 + hh*4];
                unsigned am = am_s[i];
                float* wdst = &w_s[hh*W_PS + jg*4*W_JS + i];
#pragma unroll
                for (int q = 0; q < 4; q++) {
                    int j = jg*4 + q;
                    float4 tv = *(const float4*)&tuv_s[j*16 + hh*4];
                    float e = (tv.x >= pq.x) ? pq.y*tv.y : pq.z*tv.z;
                    wdst[q*W_JS] = (am & (1u << j)) ? e : 0.f;
                }
            }
        }
        __syncthreads();
        // phase 3: GEMM over the 32-j tile
#pragma unroll 2
        for (int j = 0; j < TJ; j++) {
            float4 xa = *(const float4*)&xh_s[j*128 + k0];
            float4 xb = *(const float4*)&xh_s[j*128 + k0 + 4];
            u64 xp[8];
            PACK2(xp[0], __float_as_uint(xa.x), __float_as_uint(xa.x));
            PACK2(xp[1], __float_as_uint(xa.y), __float_as_uint(xa.y));
            PACK2(xp[2], __float_as_uint(xa.z), __float_as_uint(xa.z));
            PACK2(xp[3], __float_as_uint(xa.w), __float_as_uint(xa.w));
            PACK2(xp[4], __float_as_uint(xb.x), __float_as_uint(xb.x));
            PACK2(xp[5], __float_as_uint(xb.y), __float_as_uint(xb.y));
            PACK2(xp[6], __float_as_uint(xb.z), __float_as_uint(xb.z));
            PACK2(xp[7], __float_as_uint(xb.w), __float_as_uint(xb.w));
            const float* wj = wrd + j*W_JS;
#pragma unroll
            for (int ip = 0; ip < 4; ip++) {
                u64 wpair = *(const u64*)&wj[ip*2];
                ADD2(denp[ip], wpair);
#pragma unroll
                for (int k = 0; k < 8; k++) FMA2(accp[ip][k], wpair, xp[k]);
            }
        }
    }

    // epilogue
    float inv[8];
#pragma unroll
    for (int ip = 0; ip < 4; ip++) {
        unsigned dl, dh;
        UNPACK2(dl, dh, denp[ip]);
        inv[ip*2+0] = 1.f / fmaxf(__uint_as_float(dl), 1e-30f);
        inv[ip*2+1] = 1.f / fmaxf(__uint_as_float(dh), 1e-30f);
    }
#pragma unroll
    for (int q = 0; q < 8; q++) {
        int ip = q >> 1, sub = q & 1;
        size_t row = rbase + i0 + it8 + q;
        float4 r0 = *(const float4*)&g_x[row*POUT + k0];
        float4 r1 = *(const float4*)&g_x[row*POUT + k0 + 4];
        float o[8];
#pragma unroll
        for (int k = 0; k < 8; k++) {
            unsigned lo, hi;
            UNPACK2(lo, hi, accp[ip][k]);
            o[k] = __uint_as_float(sub ? hi : lo);
        }
        float4 w0, w1;
        w0.x = fmaxf(o[0]*inv[q], 0.f) + r0.x;
        w0.y = fmaxf(o[1]*inv[q], 0.f) + r0.y;
        w0.z = fmaxf(o[2]*inv[q], 0.f) + r0.z;
        w0.w = fmaxf(o[3]*inv[q], 0.f) + r0.w;
        w1.x = fmaxf(o[4]*inv[q], 0.f) + r1.x;
        w1.y = fmaxf(o[5]*inv[q], 0.f) + r1.y;
        w1.z = fmaxf(o[6]*inv[q], 0.f) + r1.z;
        w1.w = fmaxf(o[7]*inv[q], 0.f) + r1.w;
        *(float4*)&g_G[row*POUT + k0]     = w0;
        *(float4*)&g_G[row*POUT + k0 + 4] = w1;
    }
}

// ---------------------------------------------------------------------------
// GAGA pooling (both branches) + LED head + log_softmax.  One block per bt.
// ---------------------------------------------------------------------------
__global__ __launch_bounds__(1024) void gagaled_kernel(
    const float* __restrict__ convW, const float* __restrict__ convb,
    const float* __restrict__ W1, const float* __restrict__ b1,
    const float* __restrict__ W2, const float* __restrict__ b2,
    float* __restrict__ out)
{
    __shared__ float hv[2][128];
    __shared__ float pool[2][128];
    __shared__ float sc[NN];
    __shared__ float red[1024];
    __shared__ float cat[512];
    __shared__ float hx[128];

    const int bt = blockIdx.x;
    const int tid = threadIdx.x, warp = tid >> 5, lane = tid & 31;

    if (tid < 256) hv[tid >> 7][tid & 127] = g_hgge[((tid >> 7)*BT + bt)*FOUT + (tid & 127)];

    for (int br = 0; br < 2; br++) {
        const float* Gp = g_G + (size_t)(br*BT + bt) * NN * POUT;
        __syncthreads();
        for (int r = warp; r < NN; r += 32) {
            float4 g = *(const float4*)&Gp[(size_t)r*POUT + lane*4];
            float a = g.x*hv[br][lane*4+0] + g.y*hv[br][lane*4+1]
                    + g.z*hv[br][lane*4+2] + g.w*hv[br][lane*4+3];
#pragma unroll
            for (int off = 16; off; off >>= 1) a += __shfl_xor_sync(0xffffffffu, a, off);
            if (lane == 0) sc[r] = a;
        }
        __syncthreads();
        float lm = -1e30f;
        for (int n = tid; n < NN; n += 1024) lm = fmaxf(lm, sc[n]);
        red[tid] = lm; __syncthreads();
        for (int s = 512; s; s >>= 1) {
            if (tid < s) red[tid] = fmaxf(red[tid], red[tid+s]);
            __syncthreads();
        }
        float mx = red[0]; __syncthreads();
        float ls = 0.f;
        for (int n = tid; n < NN; n += 1024) {
            float e = __expf(sc[n] - mx);
            sc[n] = e;
            ls += e;
        }
        red[tid] = ls; __syncthreads();
        for (int s = 512; s; s >>= 1) {
            if (tid < s) red[tid] += red[tid+s];
            __syncthreads();
        }
        float winv = 1.f / red[0]; __syncthreads();
        const int seg = tid >> 7, d = tid & 127;
        float acc = 0.f;
        const int n0 = seg * 256;
#pragma unroll 8
        for (int n = n0; n < n0 + 256; n++) acc += Gp[(size_t)n*POUT + d] * sc[n];
        red[tid] = acc; __syncthreads();
        if (tid < 128) {
            float s = 0.f;
#pragma unroll
            for (int g = 0; g < 8; g++) s += red[g*128 + d];
            pool[br][d] = s * winv;
        }
    }
    __syncthreads();
    for (int o = warp; o < 256; o += 32) {
        float va = 0.f, vb = 0.f;
        for (int k = lane; k < 256; k += 32) {
            float w  = convW[(size_t)o*256 + k];
            float eav = (k < 128) ? hv[0][k] : pool[0][k-128];
            float ebv = (k < 128) ? hv[1][k] : pool[1][k-128];
            va += eav * w; vb += ebv * w;
        }
#pragma unroll
        for (int off = 16; off; off >>= 1) {
            va += __shfl_xor_sync(0xffffffffu, va, off);
            vb += __shfl_xor_sync(0xffffffffu, vb, off);
        }
        if (lane == 0) cat[o] = fmaxf(va, vb) + convb[o];
    }
    if (tid < 256) {
        float eav = (tid < 128) ? hv[0][tid] : pool[0][tid-128];
        float ebv = (tid < 128) ? hv[1][tid] : pool[1][tid-128];
        cat[256 + tid] = eav - ebv;
    }
    __syncthreads();
    for (int o = warp; o < 128; o += 32) {
        float acc = 0.f;
        for (int k = lane; k < 512; k += 32) acc += cat[k] * W1[(size_t)o*512 + k];
#pragma unroll
        for (int off = 16; off; off >>= 1) acc += __shfl_xor_sync(0xffffffffu, acc, off);
        if (lane == 0) hx[o] = fmaxf(acc + b1[o], 0.f);
    }
    __syncthreads();
    if (warp < 2) {
        float acc = 0.f;
        for (int k = lane; k < 128; k += 32) acc += hx[k] * W2[warp*128 + k];
#pragma unroll
        for (int off = 16; off; off >>= 1) acc += __shfl_xor_sync(0xffffffffu, acc, off);
        if (lane == 0) red[warp] = acc + b2[warp];
    }
    __syncthreads();
    if (tid == 0) {
        float l0 = red[0], l1 = red[1];
        float m = fmaxf(l0, l1);
        float lse = m + logf(__expf(l0-m) + __expf(l1-m));
        out[bt*2 + 0] = l0 - lse;
        out[bt*2 + 1] = l1 - lse;
    }
}

// ---------------------------------------------------------------------------
extern "C" void kernel_launch(void* const* d_in, const int* in_sizes, int n_in,
                              void* d_out, int out_size)
{
    const float* a      = (const float*)d_in[0];
    const float* bio_a  = (const float*)d_in[1];
    const int*   Aadj   = (const int*)  d_in[2];
    const float* b      = (const float*)d_in[3];
    const float* bio_b  = (const float*)d_in[4];
    const int*   Badj   = (const int*)  d_in[5];
    const float* initW  = (const float*)d_in[6];
    const float* initb  = (const float*)d_in[7];
    const float* projW  = (const float*)d_in[8];
    const float* attw   = (const float*)d_in[9];
    const float* attb   = (const float*)d_in[10];
    const float* ggeW1  = (const float*)d_in[11];
    const float* ggeb1  = (const float*)d_in[12];
    const float* ggeW2  = (const float*)d_in[13];
    const float* ggeb2  = (const float*)d_in[14];
    const float* convW  = (const float*)d_in[15];
    const float* convb  = (const float*)d_in[16];
    const float* ledW1  = (const float*)d_in[17];
    const float* ledb1  = (const float*)d_in[18];
    const float* ledW2  = (const float*)d_in[19];
    const float* ledb2  = (const float*)d_in[20];
    float* out = (float*)d_out;

    cudaFuncSetAttribute(attn_dense, cudaFuncAttributeMaxDynamicSharedMemorySize,
                         SM_BYTES);

    gemm_tn<<<dim3(BT*NN/64, 2), 256>>>(bio_a, bio_b, initW, initb,
                                        nullptr, nullptr, PIN, 0);
    gemm_tn<<<dim3(BT*NN/64, 2), 256>>>(nullptr, nullptr, projW, nullptr,
                                        attw, attb, POUT, 1);
    gge_kernel<<<dim3(BT, 2), 512>>>(a, b, ggeW1, ggeb1, ggeW2, ggeb2);
    attn_dense<<<dim3(NN/128, BT, 2), 256, SM_BYTES>>>(Aadj, Badj);
    gagaled_kernel<<<BT, 1024>>>(convW, convb, ledW1, ledb1, ledW2, ledb2, out);
}

// round 6
// speedup vs baseline: 1.1152x; 1.1152x over previous
#include <cuda_runtime.h>
#include <cstdint>
#include <cstddef>

// Problem constants
#define BT    4
#define NN    2048
#define FIN   512
#define FOUT  128
#define PIN   256
#define POUT  128
#define HEAD  4
#define KD    32           // per-head dim

typedef unsigned long long u64;

// Scratch (device globals; no allocation allowed)
__device__ float g_x   [2*BT*NN*POUT];   // init linear output (residual source)
__device__ float g_xh  [2*BT*NN*POUT];   // proj output (per-head features)
__device__ float g_G   [2*BT*NN*POUT];   // PPIGE output
__device__ float g_pqs4[2*BT*NN*16];     // per row i, head h: {-s1, e^{s1}, e^{.2 s1}, 0}
__device__ float g_tuv4[2*BT*NN*16];     // per col j, head h: {t, e^{t}, e^{.2 t}, 0}
__device__ float g_hgge[2*BT*FOUT];
__device__ float g_h1  [2*BT*128];
__device__ float g_pool[2*BT*FOUT];

// f32x2 packed math
#define PACK2(d, lo, hi) asm("mov.b64 %0, {%1, %2};" : "=l"(d) : "r"(lo), "r"(hi))
#define UNPACK2(lo, hi, s) asm("mov.b64 {%0, %1}, %2;" : "=r"(lo), "=r"(hi) : "l"(s))
#define FMA2(d, a, b) asm("fma.rn.f32x2 %0, %1, %2, %0;" : "+l"(d) : "l"(a), "l"(b))

// ---------------------------------------------------------------------------
// C[r][c] = sum_k A[r][k]*W[c][k] (+bias).  BM=64, 128 cols, BK=16.
// mode 0: A = bio_{a,b}, C = g_x.
// mode 1: A = g_x, C = g_xh, fused epilogue computes attention scalars.
// ---------------------------------------------------------------------------
__global__ __launch_bounds__(256) void gemm_tn(
    const float* __restrict__ A0, const float* __restrict__ A1,
    const float* __restrict__ W,  const float* __restrict__ bias,
    const float* __restrict__ attw, const float* __restrict__ attb,
    int Kdim, int mode)
{
    __shared__ float As[16][65];
    __shared__ float Ws[16][128];

    const int branch = blockIdx.y;
    const float* Ain;
    float* Cout;
    if (mode == 0) { Ain = branch ? A1 : A0;                   Cout = g_x;  }
    else           { Ain = g_x + (size_t)branch * BT*NN*POUT;  Cout = g_xh; }
    Cout += (size_t)branch * BT*NN*POUT;

    const int row0 = blockIdx.x * 64;
    const int tid  = threadIdx.x;
    const int tx   = tid & 31;      // lane: col group (4 cols)
    const int ty   = tid >> 5;      // warp: row group (8 rows)

    float acc[8][4];
#pragma unroll
    for (int i = 0; i < 8; i++)
#pragma unroll
        for (int j = 0; j < 4; j++) acc[i][j] = 0.f;

    for (int k0 = 0; k0 < Kdim; k0 += 16) {
        {   // A tile: 64x16
            int r = tid >> 2, kq = tid & 3;
            float4 v = *(const float4*)&Ain[(size_t)(row0 + r)*Kdim + k0 + kq*4];
            As[kq*4+0][r] = v.x; As[kq*4+1][r] = v.y;
            As[kq*4+2][r] = v.z; As[kq*4+3][r] = v.w;
        }
        {   // W tile: 128x16
            int c = tid >> 1, kh = tid & 1;
#pragma unroll
            for (int p = 0; p < 2; p++) {
                int kk = kh*8 + p*4;
                float4 v = *(const float4*)&W[(size_t)c*Kdim + k0 + kk];
                Ws[kk+0][c] = v.x; Ws[kk+1][c] = v.y;
                Ws[kk+2][c] = v.z; Ws[kk+3][c] = v.w;
            }
        }
        __syncthreads();
#pragma unroll
        for (int k = 0; k < 16; k++) {
            float4 wv = *(const float4*)&Ws[k][tx*4];
            float av[8];
#pragma unroll
            for (int i = 0; i < 8; i++) av[i] = As[k][ty*8 + i];
#pragma unroll
            for (int i = 0; i < 8; i++) {
                acc[i][0] += av[i]*wv.x; acc[i][1] += av[i]*wv.y;
                acc[i][2] += av[i]*wv.z; acc[i][3] += av[i]*wv.w;
            }
        }
        __syncthreads();
    }
    float4 bv = make_float4(0.f, 0.f, 0.f, 0.f);
    if (bias) bv = *(const float4*)&bias[tx*4];
#pragma unroll
    for (int i = 0; i < 8; i++) {
        float4 o = make_float4(acc[i][0]+bv.x, acc[i][1]+bv.y,
                               acc[i][2]+bv.z, acc[i][3]+bv.w);
        *(float4*)&Cout[(size_t)(row0 + ty*8 + i)*POUT + tx*4] = o;
    }

    if (mode == 1) {
        const int h = tx >> 3, lq = tx & 7;
        float w1[4], w2[4];
#pragma unroll
        for (int q = 0; q < 4; q++) {
            w1[q] = attw[h*2*KD + lq*4 + q];
            w2[q] = attw[h*2*KD + KD + lq*4 + q];
        }
        const float bb = attb[h];
#pragma unroll
        for (int i = 0; i < 8; i++) {
            float p1 = acc[i][0]*w1[0] + acc[i][1]*w1[1]
                     + acc[i][2]*w1[2] + acc[i][3]*w1[3];
            float p2 = acc[i][0]*w2[0] + acc[i][1]*w2[1]
                     + acc[i][2]*w2[2] + acc[i][3]*w2[3];
#pragma unroll
            for (int off = 1; off < 8; off <<= 1) {
                p1 += __shfl_xor_sync(0xffffffffu, p1, off);
                p2 += __shfl_xor_sync(0xffffffffu, p2, off);
            }
            if (lq == 0) {
                size_t r = (size_t)branch*BT*NN + row0 + ty*8 + i;
                float s1 = p1, t = p2 + bb;
                float* pq = &g_pqs4[r*16 + h*4];
                pq[0] = -s1;
                pq[1] = __expf(s1);
                pq[2] = __expf(0.2f*s1);
                float* tv = &g_tuv4[r*16 + h*4];
                tv[0] = t;
                tv[1] = __expf(t);
                tv[2] = __expf(0.2f*t);
            }
        }
    }
}

// ---------------------------------------------------------------------------
// GGE split: layer 1 (16 blocks, W1 read once, all 8 samples per block)
// ---------------------------------------------------------------------------
__global__ __launch_bounds__(256) void gge1_kernel(
    const float* __restrict__ a, const float* __restrict__ b,
    const float* __restrict__ W1, const float* __restrict__ b1)
{
    __shared__ float in_s[8][FIN];
    const int tid = threadIdx.x, warp = tid >> 5, lane = tid & 31;
#pragma unroll
    for (int p = 0; p < 16; p++) {
        int idx = tid + p*256;
        int s = idx >> 9, k = idx & 511;
        in_s[s][k] = ((s >> 2) ? b : a)[(s & 3)*FIN + k];
    }
    __syncthreads();
    const int o = blockIdx.x * 8 + warp;
    const float* w = W1 + (size_t)o*FIN;
    float wr[16];
#pragma unroll
    for (int q = 0; q < 16; q++) wr[q] = w[lane + q*32];
    const float bo = b1[o];
#pragma unroll
    for (int s = 0; s < 8; s++) {
        float acc = 0.f;
#pragma unroll
        for (int q = 0; q < 16; q++) acc += wr[q] * in_s[s][lane + q*32];
#pragma unroll
        for (int off = 16; off; off >>= 1) acc += __shfl_xor_sync(0xffffffffu, acc, off);
        if (lane == 0) g_h1[s*128 + o] = fmaxf(acc + bo, 0.f);
    }
}

// layer 2 (16 blocks)
__global__ __launch_bounds__(256) void gge2_kernel(
    const float* __restrict__ W2, const float* __restrict__ b2)
{
    __shared__ float in_s[8][128];
    const int tid = threadIdx.x, warp = tid >> 5, lane = tid & 31;
#pragma unroll
    for (int p = 0; p < 4; p++) {
        int idx = tid + p*256;
        int s = idx >> 7, k = idx & 127;
        in_s[s][k] = g_h1[s*128 + k];
    }
    __syncthreads();
    const int o = blockIdx.x * 8 + warp;
    const float* w = W2 + (size_t)o*128;
    float wr[4];
#pragma unroll
    for (int q = 0; q < 4; q++) wr[q] = w[lane + q*32];
    const float bo = b2[o];
#pragma unroll
    for (int s = 0; s < 8; s++) {
        float acc = 0.f;
#pragma unroll
        for (int q = 0; q < 4; q++) acc += wr[q] * in_s[s][lane + q*32];
#pragma unroll
        for (int off = 16; off; off >>= 1) acc += __shfl_xor_sync(0xffffffffu, acc, off);
        if (lane == 0) g_hgge[s*128 + o] = fmaxf(acc + bo, 0.f);
    }
}

// ---------------------------------------------------------------------------
// Dense register-tiled attention GEMM: out = relu( (w @ xh) / rowsum(w) ) + x
// CTA: 128 i x 128 k, 512 threads; thread (ti=tid>>4: 4 i-rows, tk=tid&15: 8 k).
// Staging role: thread = (hs=tid>>7, is=tid&127) computes w and den.
// xh smem: k-group g at word g*10 (row 160 words) -> conflict-free LDS.64.
// w smem: [h][j][i], plane stride 4232 (mod 32 == 8) -> conflict-free LDS.128.
// ---------------------------------------------------------------------------
#define TJ 32
#define W_PS 4232
#define W_JS 132
#define XH_OFF (4*W_PS)              // 16928
#define XH_JS 160
#define TUV_OFF (XH_OFF + TJ*XH_JS)  // 22048
#define AM_OFF (TUV_OFF + TJ*16)     // 22560
#define DEN_OFF (AM_OFF + 128)       // 22688
#define SM_FLOATS (DEN_OFF + 512)    // 23200
#define SM_BYTES (SM_FLOATS*4)       // 92800

__global__ __launch_bounds__(512) void attn_dense(
    const int* __restrict__ A0, const int* __restrict__ A1)
{
    extern __shared__ float sm[];
    float* w_s   = sm;
    float* xh_s  = sm + XH_OFF;
    float* tuv_s = sm + TUV_OFF;
    unsigned* am_s = (unsigned*)(sm + AM_OFF);
    float* den_s = sm + DEN_OFF;

    const int branch = blockIdx.z, b = blockIdx.y;
    const int i0 = blockIdx.x * 128;
    const int tid = threadIdx.x, warp = tid >> 5, lane = tid & 31;
    const int ti = tid >> 4, tk = tid & 15;          // GEMM role
    const int hg = tk >> 2, k0 = tk * 8;
    const int hs = tid >> 7, is = tid & 127;         // staging role

    const size_t rbase = (size_t)(branch*BT + b) * NN;
    const float* xhb = g_xh + rbase * POUT;
    const float* tvb = g_tuv4 + rbase * 16;
    const int* Abase = (branch ? A1 : A0) + ((size_t)b*NN + i0) * NN;

    const float4 pq = *(const float4*)&g_pqs4[(rbase + i0 + is)*16 + hs*4];
    float den = 0.f;

    u64 acc[4][4];
#pragma unroll
    for (int r = 0; r < 4; r++)
#pragma unroll
        for (int q = 0; q < 4; q++) acc[r][q] = 0ull;

    const float* wrd = w_s + hg*W_PS + ti*4;
    float* wwr = w_s + hs*W_PS + is;
    const float* xrd = xh_s + tk*10;

    for (int jt = 0; jt < NN; jt += TJ) {
        __syncthreads();
        {   // adjacency ballots: warp covers rows warp*8 .. +7
            const int* Ar = Abase + (size_t)(warp*8)*NN + jt + lane;
#pragma unroll
            for (int r = 0; r < 8; r++) {
                int v = Ar[(size_t)r*NN];
                unsigned m = __ballot_sync(0xffffffffu, v != 0);
                if (lane == 0) am_s[warp*8 + r] = m;
            }
        }
        if (tid < 128) {    // tuv: 32 j x 4 float4
            int j = tid >> 2, c = tid & 3;
            *(float4*)&tuv_s[j*16 + c*4] =
                *(const float4*)&tvb[(size_t)(jt + j)*16 + c*4];
        }
#pragma unroll
        for (int p = 0; p < 2; p++) {   // xh: 1024 float4, padded k-groups
            int idx = tid + p*512;
            int j = idx >> 5, c = idx & 31;
            float4 v = *(const float4*)&xhb[(size_t)(jt + j)*POUT + c*4];
            float* dst = &xh_s[j*XH_JS + (c >> 1)*10 + (c & 1)*4];
            *(float2*)dst       = make_float2(v.x, v.y);
            *(float2*)(dst + 2) = make_float2(v.z, v.w);
        }
        __syncthreads();
        {   // w field: thread (hs, is) over 32 j; den rides along
            const unsigned am = am_s[is];
#pragma unroll 8
            for (int j = 0; j < TJ; j++) {
                float4 tv = *(const float4*)&tuv_s[j*16 + hs*4];
                float e = (tv.x >= pq.x) ? pq.y*tv.y : pq.z*tv.z;
                e = ((am >> j) & 1u) ? e : 0.f;
                wwr[j*W_JS] = e;
                den += e;
            }
        }
        __syncthreads();
        // GEMM over the 32-j tile
#pragma unroll 2
        for (int j = 0; j < TJ; j++) {
            float4 wv = *(const float4*)&wrd[j*W_JS];
            const float* xp = xrd + j*XH_JS;
            u64 x0 = *(const u64*)(xp);
            u64 x1 = *(const u64*)(xp + 2);
            u64 x2 = *(const u64*)(xp + 4);
            u64 x3 = *(const u64*)(xp + 6);
            u64 w0, w1, w2, w3;
            PACK2(w0, __float_as_uint(wv.x), __float_as_uint(wv.x));
            PACK2(w1, __float_as_uint(wv.y), __float_as_uint(wv.y));
            PACK2(w2, __float_as_uint(wv.z), __float_as_uint(wv.z));
            PACK2(w3, __float_as_uint(wv.w), __float_as_uint(wv.w));
            FMA2(acc[0][0], w0, x0); FMA2(acc[0][1], w0, x1);
            FMA2(acc[0][2], w0, x2); FMA2(acc[0][3], w0, x3);
            FMA2(acc[1][0], w1, x0); FMA2(acc[1][1], w1, x1);
            FMA2(acc[1][2], w1, x2); FMA2(acc[1][3], w1, x3);
            FMA2(acc[2][0], w2, x0); FMA2(acc[2][1], w2, x1);
            FMA2(acc[2][2], w2, x2); FMA2(acc[2][3], w2, x3);
            FMA2(acc[3][0], w3, x0); FMA2(acc[3][1], w3, x1);
            FMA2(acc[3][2], w3, x2); FMA2(acc[3][3], w3, x3);
        }
    }

    den_s[hs*128 + is] = den;
    __syncthreads();
    float4 dv = *(const float4*)&den_s[hg*128 + ti*4];
    float dinv[4];
    dinv[0] = 1.f / fmaxf(dv.x, 1e-30f);
    dinv[1] = 1.f / fmaxf(dv.y, 1e-30f);
    dinv[2] = 1.f / fmaxf(dv.z, 1e-30f);
    dinv[3] = 1.f / fmaxf(dv.w, 1e-30f);

#pragma unroll
    for (int r = 0; r < 4; r++) {
        size_t row = rbase + i0 + ti*4 + r;
        float4 x0 = *(const float4*)&g_x[row*POUT + k0];
        float4 x1 = *(const float4*)&g_x[row*POUT + k0 + 4];
        float o[8];
#pragma unroll
        for (int q = 0; q < 4; q++) {
            unsigned lo, hi;
            UNPACK2(lo, hi, acc[r][q]);
            o[2*q]   = __uint_as_float(lo);
            o[2*q+1] = __uint_as_float(hi);
        }
        float4 w0, w1;
        w0.x = fmaxf(o[0]*dinv[r], 0.f) + x0.x;
        w0.y = fmaxf(o[1]*dinv[r], 0.f) + x0.y;
        w0.z = fmaxf(o[2]*dinv[r], 0.f) + x0.z;
        w0.w = fmaxf(o[3]*dinv[r], 0.f) + x0.w;
        w1.x = fmaxf(o[4]*dinv[r], 0.f) + x1.x;
        w1.y = fmaxf(o[5]*dinv[r], 0.f) + x1.y;
        w1.z = fmaxf(o[6]*dinv[r], 0.f) + x1.z;
        w1.w = fmaxf(o[7]*dinv[r], 0.f) + x1.w;
        *(float4*)&g_G[row*POUT + k0]     = w0;
        *(float4*)&g_G[row*POUT + k0 + 4] = w1;
    }
}

// ---------------------------------------------------------------------------
// GAGA pooling: grid (BT, 2), writes g_pool.
// ---------------------------------------------------------------------------
__global__ __launch_bounds__(1024) void gaga_kernel()
{
    __shared__ float hv[128];
    __shared__ float sc[NN];
    __shared__ float red[1024];
    const int bt = blockIdx.x, br = blockIdx.y;
    const int base = br*BT + bt;
    const float* Gp = g_G + (size_t)base * NN * POUT;
    const int tid = threadIdx.x, warp = tid >> 5, lane = tid & 31;

    if (tid < 128) hv[tid] = g_hgge[base*FOUT + tid];
    __syncthreads();
    for (int r = warp; r < NN; r += 32) {
        float4 g = *(const float4*)&Gp[(size_t)r*POUT + lane*4];
        float a = g.x*hv[lane*4+0] + g.y*hv[lane*4+1]
                + g.z*hv[lane*4+2] + g.w*hv[lane*4+3];
#pragma unroll
        for (int off = 16; off; off >>= 1) a += __shfl_xor_sync(0xffffffffu, a, off);
        if (lane == 0) sc[r] = a;
    }
    __syncthreads();
    float lm = -1e30f;
    for (int n = tid; n < NN; n += 1024) lm = fmaxf(lm, sc[n]);
    red[tid] = lm; __syncthreads();
    for (int s = 512; s; s >>= 1) {
        if (tid < s) red[tid] = fmaxf(red[tid], red[tid+s]);
        __syncthreads();
    }
    float mx = red[0]; __syncthreads();
    float ls = 0.f;
    for (int n = tid; n < NN; n += 1024) {
        float e = __expf(sc[n] - mx);
        sc[n] = e;
        ls += e;
    }
    red[tid] = ls; __syncthreads();
    for (int s = 512; s; s >>= 1) {
        if (tid < s) red[tid] += red[tid+s];
        __syncthreads();
    }
    float winv = 1.f / red[0]; __syncthreads();
    const int seg = tid >> 7, d = tid & 127;
    float acc = 0.f;
    const int n0 = seg * 256;
#pragma unroll 8
    for (int n = n0; n < n0 + 256; n++) acc += Gp[(size_t)n*POUT + d] * sc[n];
    red[tid] = acc; __syncthreads();
    if (tid < 128) {
        float s = 0.f;
#pragma unroll
        for (int g = 0; g < 8; g++) s += red[g*128 + d];
        g_pool[base*FOUT + tid] = s * winv;
    }
}

// ---------------------------------------------------------------------------
// LED head + log_softmax.  grid BT, 256 threads.
// ---------------------------------------------------------------------------
__global__ __launch_bounds__(256) void led_kernel(
    const float* __restrict__ convW, const float* __restrict__ convb,
    const float* __restrict__ W1, const float* __restrict__ b1,
    const float* __restrict__ W2, const float* __restrict__ b2,
    float* __restrict__ out)
{
    __shared__ float ea[256], eb[256], cat[512], hx[128], lg[2];
    const int bt = blockIdx.x;
    const int tid = threadIdx.x, warp = tid >> 5, lane = tid & 31;

    if (tid < 128) {
        ea[tid]       = g_hgge[(0*BT + bt)*FOUT + tid];
        ea[128 + tid] = g_pool[(0*BT + bt)*FOUT + tid];
        eb[tid]       = g_hgge[(1*BT + bt)*FOUT + tid];
        eb[128 + tid] = g_pool[(1*BT + bt)*FOUT + tid];
    }
    __syncthreads();
    for (int o = warp; o < 256; o += 8) {
        float va = 0.f, vb = 0.f;
#pragma unroll
        for (int q = 0; q < 8; q++) {
            float w = convW[(size_t)o*256 + lane + q*32];
            va += ea[lane + q*32] * w;
            vb += eb[lane + q*32] * w;
        }
#pragma unroll
        for (int off = 16; off; off >>= 1) {
            va += __shfl_xor_sync(0xffffffffu, va, off);
            vb += __shfl_xor_sync(0xffffffffu, vb, off);
        }
        if (lane == 0) cat[o] = fmaxf(va, vb) + convb[o];
    }
    if (tid < 256) cat[256 + tid] = ea[tid] - eb[tid];
    __syncthreads();
    for (int o = warp; o < 128; o += 8) {
        float acc = 0.f;
#pragma unroll
        for (int q = 0; q < 16; q++) acc += cat[lane + q*32] * W1[(size_t)o*512 + lane + q*32];
#pragma unroll
        for (int off = 16; off; off >>= 1) acc += __shfl_xor_sync(0xffffffffu, acc, off);
        if (lane == 0) hx[o] = fmaxf(acc + b1[o], 0.f);
    }
    __syncthreads();
    if (warp < 2) {
        float acc = 0.f;
#pragma unroll
        for (int q = 0; q < 4; q++) acc += hx[lane + q*32] * W2[warp*128 + lane + q*32];
#pragma unroll
        for (int off = 16; off; off >>= 1) acc += __shfl_xor_sync(0xffffffffu, acc, off);
        if (lane == 0) lg[warp] = acc + b2[warp];
    }
    __syncthreads();
    if (tid == 0) {
        float l0 = lg[0], l1 = lg[1];
        float m = fmaxf(l0, l1);
        float lse = m + logf(__expf(l0-m) + __expf(l1-m));
        out[bt*2 + 0] = l0 - lse;
        out[bt*2 + 1] = l1 - lse;
    }
}

// ---------------------------------------------------------------------------
extern "C" void kernel_launch(void* const* d_in, const int* in_sizes, int n_in,
                              void* d_out, int out_size)
{
    const float* a      = (const float*)d_in[0];
    const float* bio_a  = (const float*)d_in[1];
    const int*   Aadj   = (const int*)  d_in[2];
    const float* b      = (const float*)d_in[3];
    const float* bio_b  = (const float*)d_in[4];
    const int*   Badj   = (const int*)  d_in[5];
    const float* initW  = (const float*)d_in[6];
    const float* initb  = (const float*)d_in[7];
    const float* projW  = (const float*)d_in[8];
    const float* attw   = (const float*)d_in[9];
    const float* attb   = (const float*)d_in[10];
    const float* ggeW1  = (const float*)d_in[11];
    const float* ggeb1  = (const float*)d_in[12];
    const float* ggeW2  = (const float*)d_in[13];
    const float* ggeb2  = (const float*)d_in[14];
    const float* convW  = (const float*)d_in[15];
    const float* convb  = (const float*)d_in[16];
    const float* ledW1  = (const float*)d_in[17];
    const float* ledb1  = (const float*)d_in[18];
    const float* ledW2  = (const float*)d_in[19];
    const float* ledb2  = (const float*)d_in[20];
    float* out = (float*)d_out;

    cudaFuncSetAttribute(attn_dense, cudaFuncAttributeMaxDynamicSharedMemorySize,
                         SM_BYTES);

    gemm_tn<<<dim3(BT*NN/64, 2), 256>>>(bio_a, bio_b, initW, initb,
                                        nullptr, nullptr, PIN, 0);
    gemm_tn<<<dim3(BT*NN/64, 2), 256>>>(nullptr, nullptr, projW, nullptr,
                                        attw, attb, POUT, 1);
    gge1_kernel<<<16, 256>>>(a, b, ggeW1, ggeb1);
    gge2_kernel<<<16, 256>>>(ggeW2, ggeb2);
    attn_dense<<<dim3(NN/128, BT, 2), 512, SM_BYTES>>>(Aadj, Badj);
    gaga_kernel<<<dim3(BT, 2), 1024>>>();
    led_kernel<<<BT, 256>>>(convW, convb, ledW1, ledb1, ledW2, ledb2, out);
}

// round 9
// speedup vs baseline: 1.9832x; 1.7783x over previous
#include <cuda_runtime.h>
#include <cstdint>
#include <cstddef>

// Problem constants
#define BT    4
#define NN    2048
#define FIN   512
#define FOUT  128
#define PIN   256
#define POUT  128
#define HEAD  4
#define KD    32           // per-head dim

typedef unsigned long long u64;

// Scratch (device globals; no allocation allowed)
__device__ float g_x   [2*BT*NN*POUT];   // init linear output (residual source)
__device__ float g_xh  [2*BT*NN*POUT];   // proj output (per-head features)
__device__ float g_G   [2*BT*NN*POUT];   // PPIGE output
__device__ float g_pqs4[2*BT*NN*16];     // per row i, head h: {-s1, e^{s1}, e^{.2 s1}, 0}
__device__ float g_tuv4[2*BT*NN*16];     // per col j, head h: {t, e^{t}, e^{.2 t}, 0}
__device__ float g_hgge[2*BT*FOUT];
__device__ float g_h1  [2*BT*128];
__device__ float g_pool[2*BT*FOUT];

#define CVT_TF32(o, i) asm("cvt.rna.tf32.f32 %0, %1;" : "=r"(o) : "f"(i))

#define MMA_TF32(d, a, bb) \
    asm("mma.sync.aligned.m16n8k8.row.col.f32.tf32.tf32.f32 " \
        "{%0,%1,%2,%3}, {%4,%5,%6,%7}, {%8,%9}, {%0,%1,%2,%3};" \
        : "+f"((d)[0]), "+f"((d)[1]), "+f"((d)[2]), "+f"((d)[3]) \
        : "r"((a)[0]), "r"((a)[1]), "r"((a)[2]), "r"((a)[3]), \
          "r"((bb)[0]), "r"((bb)[1]))

// ---------------------------------------------------------------------------
// C[r][c] = sum_k A[r][k]*W[c][k] (+bias).  BM=64, 128 cols, BK=16.
// mode 0: A = bio_{a,b}, C = g_x.
// mode 1: A = g_x, C = g_xh, fused epilogue computes attention scalars.
// ---------------------------------------------------------------------------
__global__ __launch_bounds__(256) void gemm_tn(
    const float* __restrict__ A0, const float* __restrict__ A1,
    const float* __restrict__ W,  const float* __restrict__ bias,
    const float* __restrict__ attw, const float* __restrict__ attb,
    int Kdim, int mode)
{
    __shared__ float As[16][65];
    __shared__ float Ws[16][128];

    const int branch = blockIdx.y;
    const float* Ain;
    float* Cout;
    if (mode == 0) { Ain = branch ? A1 : A0;                   Cout = g_x;  }
    else           { Ain = g_x + (size_t)branch * BT*NN*POUT;  Cout = g_xh; }
    Cout += (size_t)branch * BT*NN*POUT;

    const int row0 = blockIdx.x * 64;
    const int tid  = threadIdx.x;
    const int tx   = tid & 31;
    const int ty   = tid >> 5;

    float acc[8][4];
#pragma unroll
    for (int i = 0; i < 8; i++)
#pragma unroll
        for (int j = 0; j < 4; j++) acc[i][j] = 0.f;

    for (int k0 = 0; k0 < Kdim; k0 += 16) {
        {   // A tile: 64x16
            int r = tid >> 2, kq = tid & 3;
            float4 v = *(const float4*)&Ain[(size_t)(row0 + r)*Kdim + k0 + kq*4];
            As[kq*4+0][r] = v.x; As[kq*4+1][r] = v.y;
            As[kq*4+2][r] = v.z; As[kq*4+3][r] = v.w;
        }
        {   // W tile: 128x16
            int c = tid >> 1, kh = tid & 1;
#pragma unroll
            for (int p = 0; p < 2; p++) {
                int kk = kh*8 + p*4;
                float4 v = *(const float4*)&W[(size_t)c*Kdim + k0 + kk];
                Ws[kk+0][c] = v.x; Ws[kk+1][c] = v.y;
                Ws[kk+2][c] = v.z; Ws[kk+3][c] = v.w;
            }
        }
        __syncthreads();
#pragma unroll
        for (int k = 0; k < 16; k++) {
            float4 wv = *(const float4*)&Ws[k][tx*4];
            float av[8];
#pragma unroll
            for (int i = 0; i < 8; i++) av[i] = As[k][ty*8 + i];
#pragma unroll
            for (int i = 0; i < 8; i++) {
                acc[i][0] += av[i]*wv.x; acc[i][1] += av[i]*wv.y;
                acc[i][2] += av[i]*wv.z; acc[i][3] += av[i]*wv.w;
            }
        }
        __syncthreads();
    }
    float4 bv = make_float4(0.f, 0.f, 0.f, 0.f);
    if (bias) bv = *(const float4*)&bias[tx*4];
#pragma unroll
    for (int i = 0; i < 8; i++) {
        float4 o = make_float4(acc[i][0]+bv.x, acc[i][1]+bv.y,
                               acc[i][2]+bv.z, acc[i][3]+bv.w);
        *(float4*)&Cout[(size_t)(row0 + ty*8 + i)*POUT + tx*4] = o;
    }

    if (mode == 1) {
        const int h = tx >> 3, lq = tx & 7;
        float w1[4], w2[4];
#pragma unroll
        for (int q = 0; q < 4; q++) {
            w1[q] = attw[h*2*KD + lq*4 + q];
            w2[q] = attw[h*2*KD + KD + lq*4 + q];
        }
        const float bb = attb[h];
#pragma unroll
        for (int i = 0; i < 8; i++) {
            float p1 = acc[i][0]*w1[0] + acc[i][1]*w1[1]
                     + acc[i][2]*w1[2] + acc[i][3]*w1[3];
            float p2 = acc[i][0]*w2[0] + acc[i][1]*w2[1]
                     + acc[i][2]*w2[2] + acc[i][3]*w2[3];
#pragma unroll
            for (int off = 1; off < 8; off <<= 1) {
                p1 += __shfl_xor_sync(0xffffffffu, p1, off);
                p2 += __shfl_xor_sync(0xffffffffu, p2, off);
            }
            if (lq == 0) {
                size_t r = (size_t)branch*BT*NN + row0 + ty*8 + i;
                float s1 = p1, t = p2 + bb;
                float* pq = &g_pqs4[r*16 + h*4];
                pq[0] = -s1;
                pq[1] = __expf(s1);
                pq[2] = __expf(0.2f*s1);
                float* tv = &g_tuv4[r*16 + h*4];
                tv[0] = t;
                tv[1] = __expf(t);
                tv[2] = __expf(0.2f*t);
            }
        }
    }
}

// ---------------------------------------------------------------------------
// GGE layer 1
// ---------------------------------------------------------------------------
__global__ __launch_bounds__(256) void gge1_kernel(
    const float* __restrict__ a, const float* __restrict__ b,
    const float* __restrict__ W1, const float* __restrict__ b1)
{
    __shared__ float in_s[8][FIN];
    const int tid = threadIdx.x, warp = tid >> 5, lane = tid & 31;
#pragma unroll
    for (int p = 0; p < 16; p++) {
        int idx = tid + p*256;
        int s = idx >> 9, k = idx & 511;
        in_s[s][k] = ((s >> 2) ? b : a)[(s & 3)*FIN + k];
    }
    __syncthreads();
    const int o = blockIdx.x * 8 + warp;
    const float* w = W1 + (size_t)o*FIN;
    float wr[16];
#pragma unroll
    for (int q = 0; q < 16; q++) wr[q] = w[lane + q*32];
    const float bo = b1[o];
#pragma unroll
    for (int s = 0; s < 8; s++) {
        float acc = 0.f;
#pragma unroll
        for (int q = 0; q < 16; q++) acc += wr[q] * in_s[s][lane + q*32];
#pragma unroll
        for (int off = 16; off; off >>= 1) acc += __shfl_xor_sync(0xffffffffu, acc, off);
        if (lane == 0) g_h1[s*128 + o] = fmaxf(acc + bo, 0.f);
    }
}

// GGE layer 2
__global__ __launch_bounds__(256) void gge2_kernel(
    const float* __restrict__ W2, const float* __restrict__ b2)
{
    __shared__ float in_s[8][128];
    const int tid = threadIdx.x, warp = tid >> 5, lane = tid & 31;
#pragma unroll
    for (int p = 0; p < 4; p++) {
        int idx = tid + p*256;
        int s = idx >> 7, k = idx & 127;
        in_s[s][k] = g_h1[s*128 + k];
    }
    __syncthreads();
    const int o = blockIdx.x * 8 + warp;
    const float* w = W2 + (size_t)o*128;
    float wr[4];
#pragma unroll
    for (int q = 0; q < 4; q++) wr[q] = w[lane + q*32];
    const float bo = b2[o];
#pragma unroll
    for (int s = 0; s < 8; s++) {
        float acc = 0.f;
#pragma unroll
        for (int q = 0; q < 4; q++) acc += wr[q] * in_s[s][lane + q*32];
#pragma unroll
        for (int off = 16; off; off >>= 1) acc += __shfl_xor_sync(0xffffffffu, acc, off);
        if (lane == 0) g_hgge[s*128 + o] = fmaxf(acc + bo, 0.f);
    }
}

// ---------------------------------------------------------------------------
// Attention via tf32 mma.sync.  CTA = 128 i-rows x 128 cols, 16 warps.
// Warp (h = warp&3, ib = warp>>2) owns head h, i-rows [ib*32, ib*32+32).
// w (attention weights) are generated per-thread in registers in the exact
// m16n8k8 A-fragment layout; xh is staged in smem pre-converted to tf32.
// out = relu( (w @ xh) / rowsum(w) ) + x, rowsum in fp32 alongside w-gen.
// ---------------------------------------------------------------------------
#define XH_JS 136
__global__ __launch_bounds__(512) void attn_mma(
    const int* __restrict__ A0, const int* __restrict__ A1)
{
    __shared__ float xh_s[64 * XH_JS];       // tf32 bits
    __shared__ float tuv_s[64 * 20];
    __shared__ u64   am_s[128];

    const int branch = blockIdx.z, b = blockIdx.y;
    const int i0 = blockIdx.x * 128;
    const int tid = threadIdx.x, warp = tid >> 5, lane = tid & 31;
    const int h = warp & 3, ib = warp >> 2;
    const int g = lane >> 2, t = lane & 3;
    const int hk0 = h * 32;

    const size_t rbase = (size_t)(branch*BT + b) * NN;
    const float* xhb = g_xh + rbase * POUT;
    const float* tvb = g_tuv4 + rbase * 16;
    const int* Abase = (branch ? A1 : A0) + ((size_t)b*NN + i0) * NN;

    // per-thread row scalars (rows g + {0,8,16,24} within the i-block)
    float4 pqr[4];
#pragma unroll
    for (int r = 0; r < 4; r++)
        pqr[r] = *(const float4*)&g_pqs4[(rbase + i0 + ib*32 + g + r*8)*16 + h*4];

    float den[4] = {0.f, 0.f, 0.f, 0.f};
    float d[2][4][4];
#pragma unroll
    for (int mt = 0; mt < 2; mt++)
#pragma unroll
        for (int nt = 0; nt < 4; nt++)
#pragma unroll
            for (int q = 0; q < 4; q++) d[mt][nt][q] = 0.f;

    for (int jt = 0; jt < NN; jt += 64) {
        __syncthreads();
        {   // adjacency: warp covers rows warp*8..+7, 64 j-bits each
            const int* Ar = Abase + (size_t)(warp*8)*NN + jt;
#pragma unroll
            for (int r = 0; r < 8; r++) {
                int v0 = Ar[(size_t)r*NN + lane];
                int v1 = Ar[(size_t)r*NN + 32 + lane];
                unsigned m0 = __ballot_sync(0xffffffffu, v0 != 0);
                unsigned m1 = __ballot_sync(0xffffffffu, v1 != 0);
                if (lane == 0) am_s[warp*8 + r] = (u64)m0 | ((u64)m1 << 32);
            }
        }
        if (tid < 256) {   // tuv: 64 j x 4 float4, padded stride 20
            int j = tid >> 2, c = tid & 3;
            *(float4*)&tuv_s[j*20 + c*4] =
                *(const float4*)&tvb[(size_t)(jt + j)*16 + c*4];
        }
#pragma unroll
        for (int p = 0; p < 4; p++) {   // xh: 64 x 128, cvt to tf32 (RNA)
            int idx = tid + p*512;
            int j = idx >> 5, c = idx & 31;
            float4 v = *(const float4*)&xhb[(size_t)(jt + j)*POUT + c*4];
            uint4 o;
            CVT_TF32(o.x, v.x); CVT_TF32(o.y, v.y);
            CVT_TF32(o.z, v.z); CVT_TF32(o.w, v.w);
            *(uint4*)&xh_s[j*XH_JS + c*4] = o;
        }
        __syncthreads();

        u64 am[4];
#pragma unroll
        for (int r = 0; r < 4; r++) am[r] = am_s[ib*32 + g + r*8];

#pragma unroll 2
        for (int chunk = 0; chunk < 8; chunk++) {
            const int j0 = chunk * 8;
            float4 ta = *(const float4*)&tuv_s[(j0 + t)*20 + h*4];
            float4 tb = *(const float4*)&tuv_s[(j0 + 4 + t)*20 + h*4];

            float w[4][2];
#pragma unroll
            for (int r = 0; r < 4; r++) {
                float ea = (ta.x >= pqr[r].x) ? pqr[r].y*ta.y : pqr[r].z*ta.z;
                float eb = (tb.x >= pqr[r].x) ? pqr[r].y*tb.y : pqr[r].z*tb.z;
                ea = ((am[r] >> (j0 + t)) & 1ull) ? ea : 0.f;
                eb = ((am[r] >> (j0 + 4 + t)) & 1ull) ? eb : 0.f;
                den[r] += ea + eb;
                w[r][0] = ea; w[r][1] = eb;
            }
            unsigned a0[4], a1[4];
            CVT_TF32(a0[0], w[0][0]); CVT_TF32(a0[1], w[1][0]);
            CVT_TF32(a0[2], w[0][1]); CVT_TF32(a0[3], w[1][1]);
            CVT_TF32(a1[0], w[2][0]); CVT_TF32(a1[1], w[3][0]);
            CVT_TF32(a1[2], w[2][1]); CVT_TF32(a1[3], w[3][1]);

            const float* xr0 = &xh_s[(j0 + t)*XH_JS + hk0 + g];
            const float* xr1 = &xh_s[(j0 + 4 + t)*XH_JS + hk0 + g];
            unsigned bb[4][2];
#pragma unroll
            for (int nt = 0; nt < 4; nt++) {
                bb[nt][0] = __float_as_uint(xr0[nt*8]);
                bb[nt][1] = __float_as_uint(xr1[nt*8]);
            }
#pragma unroll
            for (int nt = 0; nt < 4; nt++) {
                MMA_TF32(d[0][nt], a0, bb[nt]);
                MMA_TF32(d[1][nt], a1, bb[nt]);
            }
        }
    }

    // quad-reduce den over t (lanes 4g..4g+3)
#pragma unroll
    for (int r = 0; r < 4; r++) {
        den[r] += __shfl_xor_sync(0xffffffffu, den[r], 1);
        den[r] += __shfl_xor_sync(0xffffffffu, den[r], 2);
    }
    float inv[4];
#pragma unroll
    for (int r = 0; r < 4; r++) inv[r] = 1.f / fmaxf(den[r], 1e-30f);

    // epilogue: D rows g + {0,8,16,24}; cols hk0 + nt*8 + 2t + {0,1}
#pragma unroll
    for (int mt = 0; mt < 2; mt++) {
#pragma unroll
        for (int half = 0; half < 2; half++) {
            const int ridx = mt*2 + half;
            const size_t row = rbase + i0 + ib*32 + g + mt*16 + half*8;
#pragma unroll
            for (int nt = 0; nt < 4; nt++) {
                const int col = hk0 + nt*8 + 2*t;
                float2 xr = *(const float2*)&g_x[row*POUT + col];
                float2 o;
                o.x = fmaxf(d[mt][nt][half*2+0]*inv[ridx], 0.f) + xr.x;
                o.y = fmaxf(d[mt][nt][half*2+1]*inv[ridx], 0.f) + xr.y;
                *(float2*)&g_G[row*POUT + col] = o;
            }
        }
    }
}

// ---------------------------------------------------------------------------
// GAGA pooling: grid (BT, 2), writes g_pool.
// ---------------------------------------------------------------------------
__global__ __launch_bounds__(1024) void gaga_kernel()
{
    __shared__ float hv[128];
    __shared__ float sc[NN];
    __shared__ float red[1024];
    const int bt = blockIdx.x, br = blockIdx.y;
    const int base = br*BT + bt;
    const float* Gp = g_G + (size_t)base * NN * POUT;
    const int tid = threadIdx.x, warp = tid >> 5, lane = tid & 31;

    if (tid < 128) hv[tid] = g_hgge[base*FOUT + tid];
    __syncthreads();
    for (int r = warp; r < NN; r += 32) {
        float4 g = *(const float4*)&Gp[(size_t)r*POUT + lane*4];
        float a = g.x*hv[lane*4+0] + g.y*hv[lane*4+1]
                + g.z*hv[lane*4+2] + g.w*hv[lane*4+3];
#pragma unroll
        for (int off = 16; off; off >>= 1) a += __shfl_xor_sync(0xffffffffu, a, off);
        if (lane == 0) sc[r] = a;
    }
    __syncthreads();
    float lm = -1e30f;
    for (int n = tid; n < NN; n += 1024) lm = fmaxf(lm, sc[n]);
    red[tid] = lm; __syncthreads();
    for (int s = 512; s; s >>= 1) {
        if (tid < s) red[tid] = fmaxf(red[tid], red[tid+s]);
        __syncthreads();
    }
    float mx = red[0]; __syncthreads();
    float ls = 0.f;
    for (int n = tid; n < NN; n += 1024) {
        float e = __expf(sc[n] - mx);
        sc[n] = e;
        ls += e;
    }
    red[tid] = ls; __syncthreads();
    for (int s = 512; s; s >>= 1) {
        if (tid < s) red[tid] += red[tid+s];
        __syncthreads();
    }
    float winv = 1.f / red[0]; __syncthreads();
    const int seg = tid >> 7, d = tid & 127;
    float acc = 0.f;
    const int n0 = seg * 256;
#pragma unroll 8
    for (int n = n0; n < n0 + 256; n++) acc += Gp[(size_t)n*POUT + d] * sc[n];
    red[tid] = acc; __syncthreads();
    if (tid < 128) {
        float s = 0.f;
#pragma unroll
        for (int g = 0; g < 8; g++) s += red[g*128 + d];
        g_pool[base*FOUT + tid] = s * winv;
    }
}

// ---------------------------------------------------------------------------
// LED head + log_softmax.  grid BT, 256 threads.
// ---------------------------------------------------------------------------
__global__ __launch_bounds__(256) void led_kernel(
    const float* __restrict__ convW, const float* __restrict__ convb,
    const float* __restrict__ W1, const float* __restrict__ b1,
    const float* __restrict__ W2, const float* __restrict__ b2,
    float* __restrict__ out)
{
    __shared__ float ea[256], eb[256], cat[512], hx[128], lg[2];
    const int bt = blockIdx.x;
    const int tid = threadIdx.x, warp = tid >> 5, lane = tid & 31;

    if (tid < 128) {
        ea[tid]       = g_hgge[(0*BT + bt)*FOUT + tid];
        ea[128 + tid] = g_pool[(0*BT + bt)*FOUT + tid];
        eb[tid]       = g_hgge[(1*BT + bt)*FOUT + tid];
        eb[128 + tid] = g_pool[(1*BT + bt)*FOUT + tid];
    }
    __syncthreads();
    for (int o = warp; o < 256; o += 8) {
        float va = 0.f, vb = 0.f;
#pragma unroll
        for (int q = 0; q < 8; q++) {
            float w = convW[(size_t)o*256 + lane + q*32];
            va += ea[lane + q*32] * w;
            vb += eb[lane + q*32] * w;
        }
#pragma unroll
        for (int off = 16; off; off >>= 1) {
            va += __shfl_xor_sync(0xffffffffu, va, off);
            vb += __shfl_xor_sync(0xffffffffu, vb, off);
        }
        if (lane == 0) cat[o] = fmaxf(va, vb) + convb[o];
    }
    if (tid < 256) cat[256 + tid] = ea[tid] - eb[tid];
    __syncthreads();
    for (int o = warp; o < 128; o += 8) {
        float acc = 0.f;
#pragma unroll
        for (int q = 0; q < 16; q++) acc += cat[lane + q*32] * W1[(size_t)o*512 + lane + q*32];
#pragma unroll
        for (int off = 16; off; off >>= 1) acc += __shfl_xor_sync(0xffffffffu, acc, off);
        if (lane == 0) hx[o] = fmaxf(acc + b1[o], 0.f);
    }
    __syncthreads();
    if (warp < 2) {
        float acc = 0.f;
#pragma unroll
        for (int q = 0; q < 4; q++) acc += hx[lane + q*32] * W2[warp*128 + lane + q*32];
#pragma unroll
        for (int off = 16; off; off >>= 1) acc += __shfl_xor_sync(0xffffffffu, acc, off);
        if (lane == 0) lg[warp] = acc + b2[warp];
    }
    __syncthreads();
    if (tid == 0) {
        float l0 = lg[0], l1 = lg[1];
        float m = fmaxf(l0, l1);
        float lse = m + logf(__expf(l0-m) + __expf(l1-m));
        out[bt*2 + 0] = l0 - lse;
        out[bt*2 + 1] = l1 - lse;
    }
}

// ---------------------------------------------------------------------------
extern "C" void kernel_launch(void* const* d_in, const int* in_sizes, int n_in,
                              void* d_out, int out_size)
{
    const float* a      = (const float*)d_in[0];
    const float* bio_a  = (const float*)d_in[1];
    const int*   Aadj   = (const int*)  d_in[2];
    const float* b      = (const float*)d_in[3];
    const float* bio_b  = (const float*)d_in[4];
    const int*   Badj   = (const int*)  d_in[5];
    const float* initW  = (const float*)d_in[6];
    const float* initb  = (const float*)d_in[7];
    const float* projW  = (const float*)d_in[8];
    const float* attw   = (const float*)d_in[9];
    const float* attb   = (const float*)d_in[10];
    const float* ggeW1  = (const float*)d_in[11];
    const float* ggeb1  = (const float*)d_in[12];
    const float* ggeW2  = (const float*)d_in[13];
    const float* ggeb2  = (const float*)d_in[14];
    const float* convW  = (const float*)d_in[15];
    const float* convb  = (const float*)d_in[16];
    const float* ledW1  = (const float*)d_in[17];
    const float* ledb1  = (const float*)d_in[18];
    const float* ledW2  = (const float*)d_in[19];
    const float* ledb2  = (const float*)d_in[20];
    float* out = (float*)d_out;

    // launch order: attn is 4th so ncu's fixed capture window lands on it
    gemm_tn<<<dim3(BT*NN/64, 2), 256>>>(bio_a, bio_b, initW, initb,
                                        nullptr, nullptr, PIN, 0);
    gemm_tn<<<dim3(BT*NN/64, 2), 256>>>(nullptr, nullptr, projW, nullptr,
                                        attw, attb, POUT, 1);
    gge1_kernel<<<16, 256>>>(a, b, ggeW1, ggeb1);
    attn_mma<<<dim3(NN/128, BT, 2), 512>>>(Aadj, Badj);
    gge2_kernel<<<16, 256>>>(ggeW2, ggeb2);
    gaga_kernel<<<dim3(BT, 2), 1024>>>();
    led_kernel<<<BT, 256>>>(convW, convb, ledW1, ledb1, ledW2, ledb2, out);
}

// round 10
// speedup vs baseline: 2.4514x; 1.2361x over previous
#include <cuda_runtime.h>
#include <cstdint>
#include <cstddef>

// Problem constants
#define BT    4
#define NN    2048
#define FIN   512
#define FOUT  128
#define PIN   256
#define POUT  128
#define HEAD  4
#define KD    32

typedef unsigned long long u64;

// Scratch (device globals; no allocation allowed)
__device__ float g_x   [2*BT*NN*POUT];   // init linear output, fp32 (residual)
__device__ float g_xh  [2*BT*NN*POUT];   // proj output, stored as tf32 bits
__device__ float g_G   [2*BT*NN*POUT];   // PPIGE output
__device__ float g_pq2 [2*BT*NN*8];      // per row, head: {P=e^{s1}, Q=e^{.2 s1}}
__device__ float g_uv2 [2*BT*NN*8];      // per col, head: {U=e^{t}, V=e^{.2 t}}
__device__ float g_hgge[2*BT*FOUT];
__device__ float g_h1  [2*BT*128];
__device__ float g_pool[2*BT*FOUT];

#define CVT_TF32(o, i) asm("cvt.rna.tf32.f32 %0, %1;" : "=r"(o) : "f"(i))

#define MMA_TF32(d, a, bb) \
    asm("mma.sync.aligned.m16n8k8.row.col.f32.tf32.tf32.f32 " \
        "{%0,%1,%2,%3}, {%4,%5,%6,%7}, {%8,%9}, {%0,%1,%2,%3};" \
        : "+f"((d)[0]), "+f"((d)[1]), "+f"((d)[2]), "+f"((d)[3]) \
        : "r"((a)[0]), "r"((a)[1]), "r"((a)[2]), "r"((a)[3]), \
          "r"((bb)[0]), "r"((bb)[1]))

// ---------------------------------------------------------------------------
// Split-tf32 GEMM: C = A @ W^T (+bias), 3-term compensation (~fp32 accuracy).
// CTA 128 rows x 128 cols, 512 thr; warp (mr=warp>>2, nc=warp&3) = 32x32 tile.
// mode 0: A = bio (Kdim=256), C = g_x (fp32).
// mode 1: A = g_x (Kdim=128), C = g_xh (tf32 bits) + attention-scalar epilogue.
// ---------------------------------------------------------------------------
#define GS 36
#define GEMM_SM_BYTES (4*128*GS*4)   // 73,728

__global__ __launch_bounds__(512) void gemm_mma(
    const float* __restrict__ A0, const float* __restrict__ A1,
    const float* __restrict__ W,  const float* __restrict__ bias,
    const float* __restrict__ attw, const float* __restrict__ attb,
    int Kdim, int mode)
{
    extern __shared__ float sg[];
    float* Ahi = sg;
    float* Alo = sg + 128*GS;
    float* Whi = sg + 2*128*GS;
    float* Wlo = sg + 3*128*GS;

    const int branch = blockIdx.y;
    const float* Ain;
    float* Cout;
    if (mode == 0) { Ain = branch ? A1 : A0;                  Cout = g_x;  }
    else           { Ain = g_x + (size_t)branch*8192*POUT;    Cout = g_xh; }
    Cout += (size_t)branch*8192*POUT;

    const int row0 = blockIdx.x * 128;
    const int tid = threadIdx.x, lane = tid & 31, warp = tid >> 5;
    const int g = lane >> 2, t = lane & 3;
    const int mr = warp >> 2, nc = warp & 3;

    float d[2][4][4];
#pragma unroll
    for (int mb = 0; mb < 2; mb++)
#pragma unroll
        for (int nt = 0; nt < 4; nt++)
#pragma unroll
            for (int q = 0; q < 4; q++) d[mb][nt][q] = 0.f;

    for (int kc = 0; kc < Kdim; kc += 32) {
        __syncthreads();
#pragma unroll
        for (int p = 0; p < 2; p++) {   // A tile 128x32
            int idx = tid + p*512, r = idx >> 3, kq = idx & 7;
            float4 v = *(const float4*)&Ain[(size_t)(row0 + r)*Kdim + kc + kq*4];
            uint4 hi, lu;
            CVT_TF32(hi.x, v.x); CVT_TF32(hi.y, v.y);
            CVT_TF32(hi.z, v.z); CVT_TF32(hi.w, v.w);
            float lx = v.x - __uint_as_float(hi.x);
            float ly = v.y - __uint_as_float(hi.y);
            float lz = v.z - __uint_as_float(hi.z);
            float lw = v.w - __uint_as_float(hi.w);
            CVT_TF32(lu.x, lx); CVT_TF32(lu.y, ly);
            CVT_TF32(lu.z, lz); CVT_TF32(lu.w, lw);
            *(uint4*)&Ahi[r*GS + kq*4] = hi;
            *(uint4*)&Alo[r*GS + kq*4] = lu;
        }
#pragma unroll
        for (int p = 0; p < 2; p++) {   // W tile 128x32
            int idx = tid + p*512, r = idx >> 3, kq = idx & 7;
            float4 v = *(const float4*)&W[(size_t)r*Kdim + kc + kq*4];
            uint4 hi, lu;
            CVT_TF32(hi.x, v.x); CVT_TF32(hi.y, v.y);
            CVT_TF32(hi.z, v.z); CVT_TF32(hi.w, v.w);
            float lx = v.x - __uint_as_float(hi.x);
            float ly = v.y - __uint_as_float(hi.y);
            float lz = v.z - __uint_as_float(hi.z);
            float lw = v.w - __uint_as_float(hi.w);
            CVT_TF32(lu.x, lx); CVT_TF32(lu.y, ly);
            CVT_TF32(lu.z, lz); CVT_TF32(lu.w, lw);
            *(uint4*)&Whi[r*GS + kq*4] = hi;
            *(uint4*)&Wlo[r*GS + kq*4] = lu;
        }
        __syncthreads();
#pragma unroll
        for (int k8 = 0; k8 < 4; k8++) {
            const int kb = k8*8;
            unsigned ahi[2][4], alo[2][4];
#pragma unroll
            for (int mb = 0; mb < 2; mb++) {
                int base = (mr*32 + mb*16 + g)*GS + kb;
                ahi[mb][0] = __float_as_uint(Ahi[base + t]);
                ahi[mb][1] = __float_as_uint(Ahi[base + 8*GS + t]);
                ahi[mb][2] = __float_as_uint(Ahi[base + t + 4]);
                ahi[mb][3] = __float_as_uint(Ahi[base + 8*GS + t + 4]);
                alo[mb][0] = __float_as_uint(Alo[base + t]);
                alo[mb][1] = __float_as_uint(Alo[base + 8*GS + t]);
                alo[mb][2] = __float_as_uint(Alo[base + t + 4]);
                alo[mb][3] = __float_as_uint(Alo[base + 8*GS + t + 4]);
            }
#pragma unroll
            for (int nt = 0; nt < 4; nt++) {
                int cb = (nc*32 + nt*8 + g)*GS + kb;
                unsigned bhi[2], blo[2];
                bhi[0] = __float_as_uint(Whi[cb + t]);
                bhi[1] = __float_as_uint(Whi[cb + t + 4]);
                blo[0] = __float_as_uint(Wlo[cb + t]);
                blo[1] = __float_as_uint(Wlo[cb + t + 4]);
#pragma unroll
                for (int mb = 0; mb < 2; mb++) {
                    MMA_TF32(d[mb][nt], ahi[mb], bhi);
                    MMA_TF32(d[mb][nt], ahi[mb], blo);
                    MMA_TF32(d[mb][nt], alo[mb], bhi);
                }
            }
        }
    }

    // epilogue
    float2 bv[4];
#pragma unroll
    for (int nt = 0; nt < 4; nt++) {
        int c = nc*32 + nt*8 + 2*t;
        if (bias) bv[nt] = *(const float2*)&bias[c];
        else      bv[nt] = make_float2(0.f, 0.f);
    }

    if (mode == 0) {
#pragma unroll
        for (int mb = 0; mb < 2; mb++)
#pragma unroll
            for (int q = 0; q < 2; q++) {
                int row = row0 + mr*32 + mb*16 + q*8 + g;
#pragma unroll
                for (int nt = 0; nt < 4; nt++) {
                    int c = nc*32 + nt*8 + 2*t;
                    float2 o = make_float2(d[mb][nt][q*2+0] + bv[nt].x,
                                           d[mb][nt][q*2+1] + bv[nt].y);
                    *(float2*)&Cout[(size_t)row*POUT + c] = o;
                }
            }
    } else {
        const int h = nc;
        float2 w1v[4], w2v[4];
#pragma unroll
        for (int nt = 0; nt < 4; nt++) {
            int lc = nt*8 + 2*t;
            w1v[nt] = *(const float2*)&attw[h*64 + lc];
            w2v[nt] = *(const float2*)&attw[h*64 + 32 + lc];
        }
        float p1[4] = {0,0,0,0}, p2[4] = {0,0,0,0};
#pragma unroll
        for (int mb = 0; mb < 2; mb++)
#pragma unroll
            for (int nt = 0; nt < 4; nt++) {
                p1[mb*2+0] += d[mb][nt][0]*w1v[nt].x + d[mb][nt][1]*w1v[nt].y;
                p1[mb*2+1] += d[mb][nt][2]*w1v[nt].x + d[mb][nt][3]*w1v[nt].y;
                p2[mb*2+0] += d[mb][nt][0]*w2v[nt].x + d[mb][nt][1]*w2v[nt].y;
                p2[mb*2+1] += d[mb][nt][2]*w2v[nt].x + d[mb][nt][3]*w2v[nt].y;
            }
        // store xh as tf32 bits
#pragma unroll
        for (int mb = 0; mb < 2; mb++)
#pragma unroll
            for (int q = 0; q < 2; q++) {
                int row = row0 + mr*32 + mb*16 + q*8 + g;
#pragma unroll
                for (int nt = 0; nt < 4; nt++) {
                    int c = nc*32 + nt*8 + 2*t;
                    unsigned o0, o1;
                    CVT_TF32(o0, d[mb][nt][q*2+0]);
                    CVT_TF32(o1, d[mb][nt][q*2+1]);
                    *(float2*)&Cout[(size_t)row*POUT + c] =
                        make_float2(__uint_as_float(o0), __uint_as_float(o1));
                }
            }
        // quad-reduce s1/s2 over t
#pragma unroll
        for (int i = 0; i < 4; i++) {
            p1[i] += __shfl_xor_sync(0xffffffffu, p1[i], 1);
            p1[i] += __shfl_xor_sync(0xffffffffu, p1[i], 2);
            p2[i] += __shfl_xor_sync(0xffffffffu, p2[i], 1);
            p2[i] += __shfl_xor_sync(0xffffffffu, p2[i], 2);
        }
        if (t == 0) {
            const float bb = attb[h];
#pragma unroll
            for (int mb = 0; mb < 2; mb++)
#pragma unroll
                for (int q = 0; q < 2; q++) {
                    int row = row0 + mr*32 + mb*16 + q*8 + g;
                    size_t gr = (size_t)branch*8192 + row;
                    float s1 = p1[mb*2+q];
                    float t2 = p2[mb*2+q] + bb;
                    *(float2*)&g_pq2[gr*8 + h*2] =
                        make_float2(__expf(s1), __expf(0.2f*s1));
                    *(float2*)&g_uv2[gr*8 + h*2] =
                        make_float2(__expf(t2), __expf(0.2f*t2));
                }
        }
    }
}

// ---------------------------------------------------------------------------
// GGE layer 1
// ---------------------------------------------------------------------------
__global__ __launch_bounds__(256) void gge1_kernel(
    const float* __restrict__ a, const float* __restrict__ b,
    const float* __restrict__ W1, const float* __restrict__ b1)
{
    __shared__ float in_s[8][FIN];
    const int tid = threadIdx.x, warp = tid >> 5, lane = tid & 31;
#pragma unroll
    for (int p = 0; p < 16; p++) {
        int idx = tid + p*256;
        int s = idx >> 9, k = idx & 511;
        in_s[s][k] = ((s >> 2) ? b : a)[(s & 3)*FIN + k];
    }
    __syncthreads();
    const int o = blockIdx.x * 8 + warp;
    const float* w = W1 + (size_t)o*FIN;
    float wr[16];
#pragma unroll
    for (int q = 0; q < 16; q++) wr[q] = w[lane + q*32];
    const float bo = b1[o];
#pragma unroll
    for (int s = 0; s < 8; s++) {
        float acc = 0.f;
#pragma unroll
        for (int q = 0; q < 16; q++) acc += wr[q] * in_s[s][lane + q*32];
#pragma unroll
        for (int off = 16; off; off >>= 1) acc += __shfl_xor_sync(0xffffffffu, acc, off);
        if (lane == 0) g_h1[s*128 + o] = fmaxf(acc + bo, 0.f);
    }
}

// GGE layer 2
__global__ __launch_bounds__(256) void gge2_kernel(
    const float* __restrict__ W2, const float* __restrict__ b2)
{
    __shared__ float in_s[8][128];
    const int tid = threadIdx.x, warp = tid >> 5, lane = tid & 31;
#pragma unroll
    for (int p = 0; p < 4; p++) {
        int idx = tid + p*256;
        int s = idx >> 7, k = idx & 127;
        in_s[s][k] = g_h1[s*128 + k];
    }
    __syncthreads();
    const int o = blockIdx.x * 8 + warp;
    const float* w = W2 + (size_t)o*128;
    float wr[4];
#pragma unroll
    for (int q = 0; q < 4; q++) wr[q] = w[lane + q*32];
    const float bo = b2[o];
#pragma unroll
    for (int s = 0; s < 8; s++) {
        float acc = 0.f;
#pragma unroll
        for (int q = 0; q < 4; q++) acc += wr[q] * in_s[s][lane + q*32];
#pragma unroll
        for (int off = 16; off; off >>= 1) acc += __shfl_xor_sync(0xffffffffu, acc, off);
        if (lane == 0) g_hgge[s*128 + o] = fmaxf(acc + bo, 0.f);
    }
}

// ---------------------------------------------------------------------------
// Attention via tf32 mma, double-buffered pipeline, predicate-free w-gen:
//   w_ij = adj * max(P_i*U_j, Q_i*V_j)       (= adj * exp(leaky(s1_i + t_j)))
// CTA 128 i x 128 cols, 16 warps (h = warp&3, ib = warp>>2).
// ---------------------------------------------------------------------------
#define XH_JS 136
#define TUV_OFF 8704            // floats (64*136)
#define AM_OFF  (TUV_OFF + 512) // 9216; 128 u64 = 256 floats
#define BUFS    (AM_OFF + 256)  // 9472 floats per buffer
#define ATTN_SM_BYTES (2*BUFS*4)  // 75,776

__device__ __forceinline__ void attn_load(
    const float* __restrict__ xhb, const float* __restrict__ uvb,
    const int* __restrict__ Abase, int jt, int tid, int warp, int lane,
    float4* pfx, float4& pft, int* pfa)
{
#pragma unroll
    for (int p = 0; p < 4; p++) {
        int idx = tid + p*512, j = idx >> 5, c = idx & 31;
        pfx[p] = *(const float4*)&xhb[(size_t)(jt + j)*POUT + c*4];
    }
    if (tid < 128) {
        int jj = tid >> 1, hf = tid & 1;
        pft = *(const float4*)&uvb[(size_t)(jt + jj)*8 + hf*4];
    }
    const int* Ar = Abase + (size_t)(warp*8)*NN + jt;
#pragma unroll
    for (int r = 0; r < 8; r++) {
        pfa[2*r]   = Ar[(size_t)r*NN + lane];
        pfa[2*r+1] = Ar[(size_t)r*NN + 32 + lane];
    }
}

__device__ __forceinline__ void attn_store(
    float* buf, int tid, int warp, int lane,
    const float4* pfx, const float4& pft, const int* pfa)
{
#pragma unroll
    for (int p = 0; p < 4; p++) {
        int idx = tid + p*512, j = idx >> 5, c = idx & 31;
        *(float4*)&buf[j*XH_JS + c*4] = pfx[p];
    }
    if (tid < 128) {
        int jj = tid >> 1, hf = tid & 1;
        *(float4*)&buf[TUV_OFF + jj*8 + hf*4] = pft;
    }
    u64* am = (u64*)(buf + AM_OFF);
#pragma unroll
    for (int r = 0; r < 8; r++) {
        unsigned m0 = __ballot_sync(0xffffffffu, pfa[2*r] != 0);
        unsigned m1 = __ballot_sync(0xffffffffu, pfa[2*r+1] != 0);
        if (lane == 0) am[warp*8 + r] = (u64)m0 | ((u64)m1 << 32);
    }
}

__global__ __launch_bounds__(512) void attn_mma(
    const int* __restrict__ A0, const int* __restrict__ A1)
{
    extern __shared__ float smA[];
    float* buf0 = smA;
    float* buf1 = smA + BUFS;

    const int branch = blockIdx.z, b = blockIdx.y;
    const int i0 = blockIdx.x * 128;
    const int tid = threadIdx.x, warp = tid >> 5, lane = tid & 31;
    const int h = warp & 3, ib = warp >> 2;
    const int g = lane >> 2, t = lane & 3;
    const int hk0 = h * 32;
    const unsigned bm1 = 1u << t, bm2 = 16u << t;

    const size_t rbase = (size_t)(branch*BT + b) * NN;
    const float* xhb = g_xh + rbase * POUT;
    const float* uvb = g_uv2 + rbase * 8;
    const int* Abase = (branch ? A1 : A0) + ((size_t)b*NN + i0) * NN;

    float2 pq[4];
#pragma unroll
    for (int r = 0; r < 4; r++)
        pq[r] = *(const float2*)&g_pq2[(rbase + i0 + ib*32 + g + r*8)*8 + h*2];

    float den[4] = {0.f, 0.f, 0.f, 0.f};
    float d[2][4][4];
#pragma unroll
    for (int mt = 0; mt < 2; mt++)
#pragma unroll
        for (int nt = 0; nt < 4; nt++)
#pragma unroll
            for (int q = 0; q < 4; q++) d[mt][nt][q] = 0.f;

    float4 pfx[4];
    float4 pft = make_float4(0.f, 0.f, 0.f, 0.f);
    int pfa[16];

    attn_load(xhb, uvb, Abase, 0, tid, warp, lane, pfx, pft, pfa);
    attn_store(buf0, tid, warp, lane, pfx, pft, pfa);
    __syncthreads();

#pragma unroll 1
    for (int it = 0; it < 32; it++) {
        float* cur = (it & 1) ? buf1 : buf0;
        float* nxt = (it & 1) ? buf0 : buf1;
        if (it < 31)
            attn_load(xhb, uvb, Abase, (it + 1)*64, tid, warp, lane, pfx, pft, pfa);

        const u64* ams = (const u64*)(cur + AM_OFF);
        u64 am[4];
#pragma unroll
        for (int r = 0; r < 4; r++) am[r] = ams[ib*32 + g + r*8];
        const float* ts = cur + TUV_OFF;

#pragma unroll
        for (int chunk = 0; chunk < 8; chunk++) {
            const int j0 = chunk * 8;
            unsigned by[4];
#pragma unroll
            for (int r = 0; r < 4; r++) by[r] = (unsigned)(am[r] >> j0);
            float2 Ua = *(const float2*)&ts[(j0 + t)*8 + h*2];
            float2 Ub = *(const float2*)&ts[(j0 + 4 + t)*8 + h*2];

            float w[4][2];
#pragma unroll
            for (int r = 0; r < 4; r++) {
                float ea = fmaxf(pq[r].x * Ua.x, pq[r].y * Ua.y);
                float eb = fmaxf(pq[r].x * Ub.x, pq[r].y * Ub.y);
                ea = (by[r] & bm1) ? ea : 0.f;
                eb = (by[r] & bm2) ? eb : 0.f;
                den[r] += ea + eb;
                w[r][0] = ea; w[r][1] = eb;
            }
            unsigned a0[4], a1[4];
            CVT_TF32(a0[0], w[0][0]); CVT_TF32(a0[1], w[1][0]);
            CVT_TF32(a0[2], w[0][1]); CVT_TF32(a0[3], w[1][1]);
            CVT_TF32(a1[0], w[2][0]); CVT_TF32(a1[1], w[3][0]);
            CVT_TF32(a1[2], w[2][1]); CVT_TF32(a1[3], w[3][1]);

            const float* xr0 = &cur[(j0 + t)*XH_JS + hk0 + g];
            const float* xr1 = &cur[(j0 + 4 + t)*XH_JS + hk0 + g];
            unsigned bb[4][2];
#pragma unroll
            for (int nt = 0; nt < 4; nt++) {
                bb[nt][0] = __float_as_uint(xr0[nt*8]);
                bb[nt][1] = __float_as_uint(xr1[nt*8]);
            }
#pragma unroll
            for (int nt = 0; nt < 4; nt++) {
                MMA_TF32(d[0][nt], a0, bb[nt]);
                MMA_TF32(d[1][nt], a1, bb[nt]);
            }
        }

        if (it < 31)
            attn_store(nxt, tid, warp, lane, pfx, pft, pfa);
        __syncthreads();
    }

    // quad-reduce den over t
#pragma unroll
    for (int r = 0; r < 4; r++) {
        den[r] += __shfl_xor_sync(0xffffffffu, den[r], 1);
        den[r] += __shfl_xor_sync(0xffffffffu, den[r], 2);
    }
    float inv[4];
#pragma unroll
    for (int r = 0; r < 4; r++) inv[r] = 1.f / fmaxf(den[r], 1e-30f);

    // epilogue: rows g + {0,8,16,24}; cols hk0 + nt*8 + 2t + {0,1}
#pragma unroll
    for (int mt = 0; mt < 2; mt++) {
#pragma unroll
        for (int half = 0; half < 2; half++) {
            const int ridx = mt*2 + half;
            const size_t row = rbase + i0 + ib*32 + g + mt*16 + half*8;
#pragma unroll
            for (int nt = 0; nt < 4; nt++) {
                const int col = hk0 + nt*8 + 2*t;
                float2 xr = *(const float2*)&g_x[row*POUT + col];
                float2 o;
                o.x = fmaxf(d[mt][nt][half*2+0]*inv[ridx], 0.f) + xr.x;
                o.y = fmaxf(d[mt][nt][half*2+1]*inv[ridx], 0.f) + xr.y;
                *(float2*)&g_G[row*POUT + col] = o;
            }
        }
    }
}

// ---------------------------------------------------------------------------
// GAGA pooling: grid (BT, 2), writes g_pool.
// ---------------------------------------------------------------------------
__global__ __launch_bounds__(1024) void gaga_kernel()
{
    __shared__ float hv[128];
    __shared__ float sc[NN];
    __shared__ float red[1024];
    const int bt = blockIdx.x, br = blockIdx.y;
    const int base = br*BT + bt;
    const float* Gp = g_G + (size_t)base * NN * POUT;
    const int tid = threadIdx.x, warp = tid >> 5, lane = tid & 31;

    if (tid < 128) hv[tid] = g_hgge[base*FOUT + tid];
    __syncthreads();
    for (int r = warp; r < NN; r += 32) {
        float4 g = *(const float4*)&Gp[(size_t)r*POUT + lane*4];
        float a = g.x*hv[lane*4+0] + g.y*hv[lane*4+1]
                + g.z*hv[lane*4+2] + g.w*hv[lane*4+3];
#pragma unroll
        for (int off = 16; off; off >>= 1) a += __shfl_xor_sync(0xffffffffu, a, off);
        if (lane == 0) sc[r] = a;
    }
    __syncthreads();
    float lm = -1e30f;
    for (int n = tid; n < NN; n += 1024) lm = fmaxf(lm, sc[n]);
    red[tid] = lm; __syncthreads();
    for (int s = 512; s; s >>= 1) {
        if (tid < s) red[tid] = fmaxf(red[tid], red[tid+s]);
        __syncthreads();
    }
    float mx = red[0]; __syncthreads();
    float ls = 0.f;
    for (int n = tid; n < NN; n += 1024) {
        float e = __expf(sc[n] - mx);
        sc[n] = e;
        ls += e;
    }
    red[tid] = ls; __syncthreads();
    for (int s = 512; s; s >>= 1) {
        if (tid < s) red[tid] += red[tid+s];
        __syncthreads();
    }
    float winv = 1.f / red[0]; __syncthreads();
    const int seg = tid >> 7, dd = tid & 127;
    float acc = 0.f;
    const int n0 = seg * 256;
#pragma unroll 8
    for (int n = n0; n < n0 + 256; n++) acc += Gp[(size_t)n*POUT + dd] * sc[n];
    red[tid] = acc; __syncthreads();
    if (tid < 128) {
        float s = 0.f;
#pragma unroll
        for (int g = 0; g < 8; g++) s += red[g*128 + dd];
        g_pool[base*FOUT + tid] = s * winv;
    }
}

// ---------------------------------------------------------------------------
// LED head + log_softmax.  grid BT, 256 threads.
// ---------------------------------------------------------------------------
__global__ __launch_bounds__(256) void led_kernel(
    const float* __restrict__ convW, const float* __restrict__ convb,
    const float* __restrict__ W1, const float* __restrict__ b1,
    const float* __restrict__ W2, const float* __restrict__ b2,
    float* __restrict__ out)
{
    __shared__ float ea[256], eb[256], cat[512], hx[128], lg[2];
    const int bt = blockIdx.x;
    const int tid = threadIdx.x, warp = tid >> 5, lane = tid & 31;

    if (tid < 128) {
        ea[tid]       = g_hgge[(0*BT + bt)*FOUT + tid];
        ea[128 + tid] = g_pool[(0*BT + bt)*FOUT + tid];
        eb[tid]       = g_hgge[(1*BT + bt)*FOUT + tid];
        eb[128 + tid] = g_pool[(1*BT + bt)*FOUT + tid];
    }
    __syncthreads();
    for (int o = warp; o < 256; o += 8) {
        float va = 0.f, vb = 0.f;
#pragma unroll
        for (int q = 0; q < 8; q++) {
            float w = convW[(size_t)o*256 + lane + q*32];
            va += ea[lane + q*32] * w;
            vb += eb[lane + q*32] * w;
        }
#pragma unroll
        for (int off = 16; off; off >>= 1) {
            va += __shfl_xor_sync(0xffffffffu, va, off);
            vb += __shfl_xor_sync(0xffffffffu, vb, off);
        }
        if (lane == 0) cat[o] = fmaxf(va, vb) + convb[o];
    }
    if (tid < 256) cat[256 + tid] = ea[tid] - eb[tid];
    __syncthreads();
    for (int o = warp; o < 128; o += 8) {
        float acc = 0.f;
#pragma unroll
        for (int q = 0; q < 16; q++) acc += cat[lane + q*32] * W1[(size_t)o*512 + lane + q*32];
#pragma unroll
        for (int off = 16; off; off >>= 1) acc += __shfl_xor_sync(0xffffffffu, acc, off);
        if (lane == 0) hx[o] = fmaxf(acc + b1[o], 0.f);
    }
    __syncthreads();
    if (warp < 2) {
        float acc = 0.f;
#pragma unroll
        for (int q = 0; q < 4; q++) acc += hx[lane + q*32] * W2[warp*128 + lane + q*32];
#pragma unroll
        for (int off = 16; off; off >>= 1) acc += __shfl_xor_sync(0xffffffffu, acc, off);
        if (lane == 0) lg[warp] = acc + b2[warp];
    }
    __syncthreads();
    if (tid == 0) {
        float l0 = lg[0], l1 = lg[1];
        float m = fmaxf(l0, l1);
        float lse = m + logf(__expf(l0-m) + __expf(l1-m));
        out[bt*2 + 0] = l0 - lse;
        out[bt*2 + 1] = l1 - lse;
    }
}

// ---------------------------------------------------------------------------
extern "C" void kernel_launch(void* const* d_in, const int* in_sizes, int n_in,
                              void* d_out, int out_size)
{
    const float* a      = (const float*)d_in[0];
    const float* bio_a  = (const float*)d_in[1];
    const int*   Aadj   = (const int*)  d_in[2];
    const float* b      = (const float*)d_in[3];
    const float* bio_b  = (const float*)d_in[4];
    const int*   Badj   = (const int*)  d_in[5];
    const float* initW  = (const float*)d_in[6];
    const float* initb  = (const float*)d_in[7];
    const float* projW  = (const float*)d_in[8];
    const float* attw   = (const float*)d_in[9];
    const float* attb   = (const float*)d_in[10];
    const float* ggeW1  = (const float*)d_in[11];
    const float* ggeb1  = (const float*)d_in[12];
    const float* ggeW2  = (const float*)d_in[13];
    const float* ggeb2  = (const float*)d_in[14];
    const float* convW  = (const float*)d_in[15];
    const float* convb  = (const float*)d_in[16];
    const float* ledW1  = (const float*)d_in[17];
    const float* ledb1  = (const float*)d_in[18];
    const float* ledW2  = (const float*)d_in[19];
    const float* ledb2  = (const float*)d_in[20];
    float* out = (float*)d_out;

    cudaFuncSetAttribute(gemm_mma, cudaFuncAttributeMaxDynamicSharedMemorySize,
                         GEMM_SM_BYTES);
    cudaFuncSetAttribute(attn_mma, cudaFuncAttributeMaxDynamicSharedMemorySize,
                         ATTN_SM_BYTES);

    // launch order: attn is 4th so the ncu capture window lands on it
    gemm_mma<<<dim3(64, 2), 512, GEMM_SM_BYTES>>>(bio_a, bio_b, initW, initb,
                                                  attw, attb, PIN, 0);
    gemm_mma<<<dim3(64, 2), 512, GEMM_SM_BYTES>>>(nullptr, nullptr, projW, nullptr,
                                                  attw, attb, POUT, 1);
    gge1_kernel<<<16, 256>>>(a, b, ggeW1, ggeb1);
    attn_mma<<<dim3(NN/128, BT, 2), 512, ATTN_SM_BYTES>>>(Aadj, Badj);
    gge2_kernel<<<16, 256>>>(ggeW2, ggeb2);
    gaga_kernel<<<dim3(BT, 2), 1024>>>();
    led_kernel<<<BT, 256>>>(convW, convb, ledW1, ledb1, ledW2, ledb2, out);
}

// round 11
// speedup vs baseline: 2.5330x; 1.0333x over previous
#include <cuda_runtime.h>
#include <cstdint>
#include <cstddef>

#define BT    4
#define NN    2048
#define FIN   512
#define FOUT  128
#define PIN   256
#define POUT  128
#define HEAD  4
#define KD    32

typedef unsigned long long u64;

// Scratch (device globals; no allocation allowed)
__device__ float g_x   [2*BT*NN*POUT];   // init linear output, fp32 (residual)
__device__ float g_xh  [2*BT*NN*POUT];   // proj output, stored as tf32 bits
__device__ float g_G   [2*BT*NN*POUT];   // PPIGE output
__device__ float g_pq2 [2*BT*NN*8];      // per row, head: {P=e^{s1}, Q=e^{.2 s1}}
__device__ float g_uv2 [2*BT*NN*8];      // per col, head: {U=e^{t}, V=e^{.2 t}}
__device__ float g_hgge[2*BT*FOUT];
__device__ float g_h1  [2*BT*128];
__device__ float g_sc  [2*BT*NN];
__device__ float g_smax[2*BT*8];
__device__ float g_esum[2*BT*8];
__device__ float g_wpart[2*BT*8*128];

#define CVT_TF32(o, i) asm("cvt.rna.tf32.f32 %0, %1;" : "=r"(o) : "f"(i))

#define MMA_TF32(d, a, bb) \
    asm("mma.sync.aligned.m16n8k8.row.col.f32.tf32.tf32.f32 " \
        "{%0,%1,%2,%3}, {%4,%5,%6,%7}, {%8,%9}, {%0,%1,%2,%3};" \
        : "+f"((d)[0]), "+f"((d)[1]), "+f"((d)[2]), "+f"((d)[3]) \
        : "r"((a)[0]), "r"((a)[1]), "r"((a)[2]), "r"((a)[3]), \
          "r"((bb)[0]), "r"((bb)[1]))

#define CP_ASYNC16(dst, src) \
    asm volatile("cp.async.cg.shared.global [%0], [%1], 16;" :: "r"(dst), "l"(src))
#define CP_COMMIT() asm volatile("cp.async.commit_group;")
#define CP_WAIT0()  asm volatile("cp.async.wait_group 0;" ::: "memory")

// ---------------------------------------------------------------------------
// Split-tf32 GEMM (3-term compensation).  CTA 128x128, 512 thr.
// mode 0: A = bio (K=256), C = g_x (fp32).
// mode 1: A = g_x (K=128), C = g_xh (tf32 bits) + attention-scalar epilogue.
// ---------------------------------------------------------------------------
#define GS 36
#define GEMM_SM_BYTES (4*128*GS*4)

__global__ __launch_bounds__(512) void gemm_mma(
    const float* __restrict__ A0, const float* __restrict__ A1,
    const float* __restrict__ W,  const float* __restrict__ bias,
    const float* __restrict__ attw, const float* __restrict__ attb,
    int Kdim, int mode)
{
    extern __shared__ float sg[];
    float* Ahi = sg;
    float* Alo = sg + 128*GS;
    float* Whi = sg + 2*128*GS;
    float* Wlo = sg + 3*128*GS;

    const int branch = blockIdx.y;
    const float* Ain;
    float* Cout;
    if (mode == 0) { Ain = branch ? A1 : A0;                  Cout = g_x;  }
    else           { Ain = g_x + (size_t)branch*8192*POUT;    Cout = g_xh; }
    Cout += (size_t)branch*8192*POUT;

    const int row0 = blockIdx.x * 128;
    const int tid = threadIdx.x, lane = tid & 31, warp = tid >> 5;
    const int g = lane >> 2, t = lane & 3;
    const int mr = warp >> 2, nc = warp & 3;

    float d[2][4][4];
#pragma unroll
    for (int mb = 0; mb < 2; mb++)
#pragma unroll
        for (int nt = 0; nt < 4; nt++)
#pragma unroll
            for (int q = 0; q < 4; q++) d[mb][nt][q] = 0.f;

    for (int kc = 0; kc < Kdim; kc += 32) {
        __syncthreads();
#pragma unroll
        for (int p = 0; p < 2; p++) {
            int idx = tid + p*512, r = idx >> 3, kq = idx & 7;
            float4 v = *(const float4*)&Ain[(size_t)(row0 + r)*Kdim + kc + kq*4];
            uint4 hi, lu;
            CVT_TF32(hi.x, v.x); CVT_TF32(hi.y, v.y);
            CVT_TF32(hi.z, v.z); CVT_TF32(hi.w, v.w);
            float lx = v.x - __uint_as_float(hi.x);
            float ly = v.y - __uint_as_float(hi.y);
            float lz = v.z - __uint_as_float(hi.z);
            float lw = v.w - __uint_as_float(hi.w);
            CVT_TF32(lu.x, lx); CVT_TF32(lu.y, ly);
            CVT_TF32(lu.z, lz); CVT_TF32(lu.w, lw);
            *(uint4*)&Ahi[r*GS + kq*4] = hi;
            *(uint4*)&Alo[r*GS + kq*4] = lu;
        }
#pragma unroll
        for (int p = 0; p < 2; p++) {
            int idx = tid + p*512, r = idx >> 3, kq = idx & 7;
            float4 v = *(const float4*)&W[(size_t)r*Kdim + kc + kq*4];
            uint4 hi, lu;
            CVT_TF32(hi.x, v.x); CVT_TF32(hi.y, v.y);
            CVT_TF32(hi.z, v.z); CVT_TF32(hi.w, v.w);
            float lx = v.x - __uint_as_float(hi.x);
            float ly = v.y - __uint_as_float(hi.y);
            float lz = v.z - __uint_as_float(hi.z);
            float lw = v.w - __uint_as_float(hi.w);
            CVT_TF32(lu.x, lx); CVT_TF32(lu.y, ly);
            CVT_TF32(lu.z, lz); CVT_TF32(lu.w, lw);
            *(uint4*)&Whi[r*GS + kq*4] = hi;
            *(uint4*)&Wlo[r*GS + kq*4] = lu;
        }
        __syncthreads();
#pragma unroll
        for (int k8 = 0; k8 < 4; k8++) {
            const int kb = k8*8;
            unsigned ahi[2][4], alo[2][4];
#pragma unroll
            for (int mb = 0; mb < 2; mb++) {
                int base = (mr*32 + mb*16 + g)*GS + kb;
                ahi[mb][0] = __float_as_uint(Ahi[base + t]);
                ahi[mb][1] = __float_as_uint(Ahi[base + 8*GS + t]);
                ahi[mb][2] = __float_as_uint(Ahi[base + t + 4]);
                ahi[mb][3] = __float_as_uint(Ahi[base + 8*GS + t + 4]);
                alo[mb][0] = __float_as_uint(Alo[base + t]);
                alo[mb][1] = __float_as_uint(Alo[base + 8*GS + t]);
                alo[mb][2] = __float_as_uint(Alo[base + t + 4]);
                alo[mb][3] = __float_as_uint(Alo[base + 8*GS + t + 4]);
            }
#pragma unroll
            for (int nt = 0; nt < 4; nt++) {
                int cb = (nc*32 + nt*8 + g)*GS + kb;
                unsigned bhi[2], blo[2];
                bhi[0] = __float_as_uint(Whi[cb + t]);
                bhi[1] = __float_as_uint(Whi[cb + t + 4]);
                blo[0] = __float_as_uint(Wlo[cb + t]);
                blo[1] = __float_as_uint(Wlo[cb + t + 4]);
#pragma unroll
                for (int mb = 0; mb < 2; mb++) {
                    MMA_TF32(d[mb][nt], ahi[mb], bhi);
                    MMA_TF32(d[mb][nt], ahi[mb], blo);
                    MMA_TF32(d[mb][nt], alo[mb], bhi);
                }
            }
        }
    }

    float2 bv[4];
#pragma unroll
    for (int nt = 0; nt < 4; nt++) {
        int c = nc*32 + nt*8 + 2*t;
        if (bias) bv[nt] = *(const float2*)&bias[c];
        else      bv[nt] = make_float2(0.f, 0.f);
    }

    if (mode == 0) {
#pragma unroll
        for (int mb = 0; mb < 2; mb++)
#pragma unroll
            for (int q = 0; q < 2; q++) {
                int row = row0 + mr*32 + mb*16 + q*8 + g;
#pragma unroll
                for (int nt = 0; nt < 4; nt++) {
                    int c = nc*32 + nt*8 + 2*t;
                    float2 o = make_float2(d[mb][nt][q*2+0] + bv[nt].x,
                                           d[mb][nt][q*2+1] + bv[nt].y);
                    *(float2*)&Cout[(size_t)row*POUT + c] = o;
                }
            }
    } else {
        const int h = nc;
        float2 w1v[4], w2v[4];
#pragma unroll
        for (int nt = 0; nt < 4; nt++) {
            int lc = nt*8 + 2*t;
            w1v[nt] = *(const float2*)&attw[h*64 + lc];
            w2v[nt] = *(const float2*)&attw[h*64 + 32 + lc];
        }
        float p1[4] = {0,0,0,0}, p2[4] = {0,0,0,0};
#pragma unroll
        for (int mb = 0; mb < 2; mb++)
#pragma unroll
            for (int nt = 0; nt < 4; nt++) {
                p1[mb*2+0] += d[mb][nt][0]*w1v[nt].x + d[mb][nt][1]*w1v[nt].y;
                p1[mb*2+1] += d[mb][nt][2]*w1v[nt].x + d[mb][nt][3]*w1v[nt].y;
                p2[mb*2+0] += d[mb][nt][0]*w2v[nt].x + d[mb][nt][1]*w2v[nt].y;
                p2[mb*2+1] += d[mb][nt][2]*w2v[nt].x + d[mb][nt][3]*w2v[nt].y;
            }
#pragma unroll
        for (int mb = 0; mb < 2; mb++)
#pragma unroll
            for (int q = 0; q < 2; q++) {
                int row = row0 + mr*32 + mb*16 + q*8 + g;
#pragma unroll
                for (int nt = 0; nt < 4; nt++) {
                    int c = nc*32 + nt*8 + 2*t;
                    unsigned o0, o1;
                    CVT_TF32(o0, d[mb][nt][q*2+0]);
                    CVT_TF32(o1, d[mb][nt][q*2+1]);
                    *(float2*)&Cout[(size_t)row*POUT + c] =
                        make_float2(__uint_as_float(o0), __uint_as_float(o1));
                }
            }
#pragma unroll
        for (int i = 0; i < 4; i++) {
            p1[i] += __shfl_xor_sync(0xffffffffu, p1[i], 1);
            p1[i] += __shfl_xor_sync(0xffffffffu, p1[i], 2);
            p2[i] += __shfl_xor_sync(0xffffffffu, p2[i], 1);
            p2[i] += __shfl_xor_sync(0xffffffffu, p2[i], 2);
        }
        if (t == 0) {
            const float bb = attb[h];
#pragma unroll
            for (int mb = 0; mb < 2; mb++)
#pragma unroll
                for (int q = 0; q < 2; q++) {
                    int row = row0 + mr*32 + mb*16 + q*8 + g;
                    size_t gr = (size_t)branch*8192 + row;
                    float s1 = p1[mb*2+q];
                    float t2 = p2[mb*2+q] + bb;
                    *(float2*)&g_pq2[gr*8 + h*2] =
                        make_float2(__expf(s1), __expf(0.2f*s1));
                    *(float2*)&g_uv2[gr*8 + h*2] =
                        make_float2(__expf(t2), __expf(0.2f*t2));
                }
        }
    }
}

// ---------------------------------------------------------------------------
// GGE layers
// ---------------------------------------------------------------------------
__global__ __launch_bounds__(256) void gge1_kernel(
    const float* __restrict__ a, const float* __restrict__ b,
    const float* __restrict__ W1, const float* __restrict__ b1)
{
    __shared__ float in_s[8][FIN];
    const int tid = threadIdx.x, warp = tid >> 5, lane = tid & 31;
#pragma unroll
    for (int p = 0; p < 16; p++) {
        int idx = tid + p*256;
        int s = idx >> 9, k = idx & 511;
        in_s[s][k] = ((s >> 2) ? b : a)[(s & 3)*FIN + k];
    }
    __syncthreads();
    const int o = blockIdx.x * 8 + warp;
    const float* w = W1 + (size_t)o*FIN;
    float wr[16];
#pragma unroll
    for (int q = 0; q < 16; q++) wr[q] = w[lane + q*32];
    const float bo = b1[o];
#pragma unroll
    for (int s = 0; s < 8; s++) {
        float acc = 0.f;
#pragma unroll
        for (int q = 0; q < 16; q++) acc += wr[q] * in_s[s][lane + q*32];
#pragma unroll
        for (int off = 16; off; off >>= 1) acc += __shfl_xor_sync(0xffffffffu, acc, off);
        if (lane == 0) g_h1[s*128 + o] = fmaxf(acc + bo, 0.f);
    }
}

__global__ __launch_bounds__(256) void gge2_kernel(
    const float* __restrict__ W2, const float* __restrict__ b2)
{
    __shared__ float in_s[8][128];
    const int tid = threadIdx.x, warp = tid >> 5, lane = tid & 31;
#pragma unroll
    for (int p = 0; p < 4; p++) {
        int idx = tid + p*256;
        int s = idx >> 7, k = idx & 127;
        in_s[s][k] = g_h1[s*128 + k];
    }
    __syncthreads();
    const int o = blockIdx.x * 8 + warp;
    const float* w = W2 + (size_t)o*128;
    float wr[4];
#pragma unroll
    for (int q = 0; q < 4; q++) wr[q] = w[lane + q*32];
    const float bo = b2[o];
#pragma unroll
    for (int s = 0; s < 8; s++) {
        float acc = 0.f;
#pragma unroll
        for (int q = 0; q < 4; q++) acc += wr[q] * in_s[s][lane + q*32];
#pragma unroll
        for (int off = 16; off; off >>= 1) acc += __shfl_xor_sync(0xffffffffu, acc, off);
        if (lane == 0) g_hgge[s*128 + o] = fmaxf(acc + bo, 0.f);
    }
}

// ---------------------------------------------------------------------------
// Attention: tf32 mma, cp.async double-buffer, den folded into MMA (ones col).
// CTA = 64 i x 128 cols, 256 thr (8 warps: h=warp&3, ib=warp>>2), 2 CTAs/SM.
// w fed to MMA as raw fp32 (HW truncates to tf32); den uses the SAME MMA w.
// ---------------------------------------------------------------------------
#define XH_JS 136
#define TUV_OFF 8704             // floats (64*136)
#define AM_OFF  (TUV_OFF + 512)  // 9216; 64 u64 = 128 floats
#define BUFS    (AM_OFF + 128)   // 9344 floats/buffer
#define ATTN_SM_BYTES (2*BUFS*4) // 74,752

__device__ __forceinline__ void attn_copy(
    float* buf, const float* __restrict__ xhb, const float* __restrict__ uvb,
    int jt, int tid)
{
    unsigned base = (unsigned)__cvta_generic_to_shared(buf);
#pragma unroll
    for (int p = 0; p < 8; p++) {
        int idx = tid + p*256, j = idx >> 5, c = idx & 31;
        unsigned dst = base + (unsigned)(j*XH_JS + c*4)*4u;
        CP_ASYNC16(dst, &xhb[(size_t)(jt + j)*POUT + c*4]);
    }
    if (tid < 128) {
        int j = tid >> 1, hf = tid & 1;
        unsigned dst = base + (unsigned)(TUV_OFF + j*8 + hf*4)*4u;
        CP_ASYNC16(dst, &uvb[(size_t)(jt + j)*8 + hf*4]);
    }
}

__global__ __launch_bounds__(256, 2) void attn_mma(
    const int* __restrict__ A0, const int* __restrict__ A1)
{
    extern __shared__ float smA[];
    float* bufs[2] = { smA, smA + BUFS };

    const int branch = blockIdx.z, b = blockIdx.y;
    const int i0 = blockIdx.x * 64;
    const int tid = threadIdx.x, warp = tid >> 5, lane = tid & 31;
    const int h = warp & 3, ib = warp >> 2;
    const int g = lane >> 2, t = lane & 3;
    const int hk0 = h * 32;
    const unsigned bm1 = 1u << t, bm2 = 16u << t;
    const unsigned one_tf = __float_as_uint(1.0f);
    const unsigned ones[2] = { one_tf, one_tf };

    const size_t rbase = (size_t)(branch*BT + b) * NN;
    const float* xhb = g_xh + rbase * POUT;
    const float* uvb = g_uv2 + rbase * 8;
    const int* Abase = (branch ? A1 : A0) + ((size_t)b*NN + i0) * NN;

    float2 pq[4];
#pragma unroll
    for (int r = 0; r < 4; r++)
        pq[r] = *(const float2*)&g_pq2[(rbase + i0 + ib*32 + g + r*8)*8 + h*2];

    float d[2][4][4];
    float d5[2][4];
#pragma unroll
    for (int mt = 0; mt < 2; mt++) {
#pragma unroll
        for (int q = 0; q < 4; q++) d5[mt][q] = 0.f;
#pragma unroll
        for (int nt = 0; nt < 4; nt++)
#pragma unroll
            for (int q = 0; q < 4; q++) d[mt][nt][q] = 0.f;
    }

    int pfa[16];
    // prologue
    attn_copy(bufs[0], xhb, uvb, 0, tid);
    CP_COMMIT();
    {
        const int* Ar = Abase + (size_t)(warp*8)*NN;
#pragma unroll
        for (int r = 0; r < 8; r++) {
            pfa[2*r]   = Ar[(size_t)r*NN + lane];
            pfa[2*r+1] = Ar[(size_t)r*NN + 32 + lane];
        }
    }

#pragma unroll 1
    for (int it = 0; it < 32; it++) {
        float* cur = bufs[it & 1];
        float* nxt = bufs[(it + 1) & 1];
        {   // adjacency masks for cur from regs
            u64* am = (u64*)(cur + AM_OFF);
#pragma unroll
            for (int r = 0; r < 8; r++) {
                unsigned m0 = __ballot_sync(0xffffffffu, pfa[2*r] != 0);
                unsigned m1 = __ballot_sync(0xffffffffu, pfa[2*r+1] != 0);
                if (lane == 0) am[warp*8 + r] = (u64)m0 | ((u64)m1 << 32);
            }
        }
        CP_WAIT0();
        __syncthreads();
        if (it < 31) {
            attn_copy(nxt, xhb, uvb, (it + 1)*64, tid);
            CP_COMMIT();
            const int* Ar = Abase + (size_t)(warp*8)*NN + (it + 1)*64;
#pragma unroll
            for (int r = 0; r < 8; r++) {
                pfa[2*r]   = Ar[(size_t)r*NN + lane];
                pfa[2*r+1] = Ar[(size_t)r*NN + 32 + lane];
            }
        }

        const u64* ams = (const u64*)(cur + AM_OFF);
        u64 am[4];
#pragma unroll
        for (int r = 0; r < 4; r++) am[r] = ams[ib*32 + g + r*8];
        const float* ts = cur + TUV_OFF;

#pragma unroll
        for (int chunk = 0; chunk < 8; chunk++) {
            const int j0 = chunk * 8;
            unsigned by[4];
#pragma unroll
            for (int r = 0; r < 4; r++) by[r] = (unsigned)(am[r] >> j0);
            float2 Ua = *(const float2*)&ts[(j0 + t)*8 + h*2];
            float2 Ub = *(const float2*)&ts[(j0 + 4 + t)*8 + h*2];

            float w[4][2];
#pragma unroll
            for (int r = 0; r < 4; r++) {
                float ea = fmaxf(pq[r].x * Ua.x, pq[r].y * Ua.y);
                float eb = fmaxf(pq[r].x * Ub.x, pq[r].y * Ub.y);
                w[r][0] = (by[r] & bm1) ? ea : 0.f;
                w[r][1] = (by[r] & bm2) ? eb : 0.f;
            }
            unsigned a0[4], a1[4];
            a0[0] = __float_as_uint(w[0][0]); a0[1] = __float_as_uint(w[1][0]);
            a0[2] = __float_as_uint(w[0][1]); a0[3] = __float_as_uint(w[1][1]);
            a1[0] = __float_as_uint(w[2][0]); a1[1] = __float_as_uint(w[3][0]);
            a1[2] = __float_as_uint(w[2][1]); a1[3] = __float_as_uint(w[3][1]);

            const float* xr0 = &cur[(j0 + t)*XH_JS + hk0 + g];
            const float* xr1 = &cur[(j0 + 4 + t)*XH_JS + hk0 + g];
            unsigned bb[4][2];
#pragma unroll
            for (int nt = 0; nt < 4; nt++) {
                bb[nt][0] = __float_as_uint(xr0[nt*8]);
                bb[nt][1] = __float_as_uint(xr1[nt*8]);
            }
#pragma unroll
            for (int nt = 0; nt < 4; nt++) {
                MMA_TF32(d[0][nt], a0, bb[nt]);
                MMA_TF32(d[1][nt], a1, bb[nt]);
            }
            MMA_TF32(d5[0], a0, ones);   // row-sum (denominator)
            MMA_TF32(d5[1], a1, ones);
        }
        __syncthreads();
    }

    // epilogue: den from d5 (cols identical); rows g+{0,8,16,24}
#pragma unroll
    for (int mt = 0; mt < 2; mt++) {
#pragma unroll
        for (int half = 0; half < 2; half++) {
            const float inv = 1.f / fmaxf(d5[mt][half*2], 1e-30f);
            const size_t row = rbase + i0 + ib*32 + g + mt*16 + half*8;
#pragma unroll
            for (int nt = 0; nt < 4; nt++) {
                const int col = hk0 + nt*8 + 2*t;
                float2 xr = *(const float2*)&g_x[row*POUT + col];
                float2 o;
                o.x = fmaxf(d[mt][nt][half*2+0]*inv, 0.f) + xr.x;
                o.y = fmaxf(d[mt][nt][half*2+1]*inv, 0.f) + xr.y;
                *(float2*)&g_G[row*POUT + col] = o;
            }
        }
    }
}

// ---------------------------------------------------------------------------
// GAGA A: scores + per-segment max.  grid (8 base, 8 seg), 256 thr.
// ---------------------------------------------------------------------------
__global__ __launch_bounds__(256) void gagaA_kernel()
{
    __shared__ float hv[128];
    __shared__ float red[8];
    const int base = blockIdx.x, seg = blockIdx.y;
    const float* Gp = g_G + (size_t)base * NN * POUT;
    const int tid = threadIdx.x, warp = tid >> 5, lane = tid & 31;

    if (tid < 128) hv[tid] = g_hgge[base*FOUT + tid];
    __syncthreads();
    const int n0 = seg * 256;
    float lmax = -1e30f;
    for (int r = n0 + warp; r < n0 + 256; r += 8) {
        float4 gg = *(const float4*)&Gp[(size_t)r*POUT + lane*4];
        float a = gg.x*hv[lane*4+0] + gg.y*hv[lane*4+1]
                + gg.z*hv[lane*4+2] + gg.w*hv[lane*4+3];
#pragma unroll
        for (int off = 16; off; off >>= 1) a += __shfl_xor_sync(0xffffffffu, a, off);
        if (lane == 0) { g_sc[base*NN + r] = a; lmax = fmaxf(lmax, a); }
    }
    if (lane == 0) red[warp] = lmax;
    __syncthreads();
    if (tid == 0) {
        float m = red[0];
#pragma unroll
        for (int i = 1; i < 8; i++) m = fmaxf(m, red[i]);
        g_smax[base*8 + seg] = m;
    }
}

// ---------------------------------------------------------------------------
// GAGA C: exp + partial expsum + partial weighted sum.  grid (8, 8), 256 thr.
// ---------------------------------------------------------------------------
__global__ __launch_bounds__(256) void gagaC_kernel()
{
    __shared__ float es[256];
    __shared__ float wred[256];
    __shared__ float mx_s;
    const int base = blockIdx.x, seg = blockIdx.y;
    const float* Gp = g_G + (size_t)base * NN * POUT;
    const int tid = threadIdx.x;

    if (tid == 0) {
        float m = g_smax[base*8];
#pragma unroll
        for (int i = 1; i < 8; i++) m = fmaxf(m, g_smax[base*8 + i]);
        mx_s = m;
    }
    __syncthreads();
    const float mx = mx_s;
    const int n0 = seg * 256;
    es[tid] = __expf(g_sc[base*NN + n0 + tid] - mx);
    __syncthreads();

    const int d = tid & 127, half = tid >> 7;
    float acc = 0.f;
    const int r0 = n0 + half*128;
#pragma unroll 8
    for (int k = 0; k < 128; k++)
        acc += Gp[(size_t)(r0 + k)*POUT + d] * es[half*128 + k];
    wred[tid] = acc;
    __syncthreads();
    if (tid < 128)
        g_wpart[(base*8 + seg)*128 + tid] = wred[tid] + wred[tid + 128];
    // expsum partial
    if (tid < 32) {
        float s = es[tid] + es[tid+32] + es[tid+64] + es[tid+96]
                + es[tid+128] + es[tid+160] + es[tid+192] + es[tid+224];
#pragma unroll
        for (int off = 16; off; off >>= 1) s += __shfl_xor_sync(0xffffffffu, s, off);
        if (tid == 0) g_esum[base*8 + seg] = s;
    }
}

// ---------------------------------------------------------------------------
// LED head + log_softmax (combines gaga partials).  grid BT, 256 thr.
// ---------------------------------------------------------------------------
__global__ __launch_bounds__(256) void led_kernel(
    const float* __restrict__ convW, const float* __restrict__ convb,
    const float* __restrict__ W1, const float* __restrict__ b1,
    const float* __restrict__ W2, const float* __restrict__ b2,
    float* __restrict__ out)
{
    __shared__ float ea[256], eb[256], cat[512], hx[128], lg[2];
    const int bt = blockIdx.x;
    const int tid = threadIdx.x, warp = tid >> 5, lane = tid & 31;

    if (tid < 128) {
#pragma unroll
        for (int br = 0; br < 2; br++) {
            const int base = br*BT + bt;
            float s = 0.f, e = 0.f;
#pragma unroll
            for (int sg = 0; sg < 8; sg++) {
                s += g_wpart[(base*8 + sg)*128 + tid];
                e += g_esum[base*8 + sg];
            }
            float pool = s / e;
            if (br == 0) { ea[tid] = g_hgge[base*FOUT + tid]; ea[128+tid] = pool; }
            else         { eb[tid] = g_hgge[base*FOUT + tid]; eb[128+tid] = pool; }
        }
    }
    __syncthreads();
    for (int o = warp; o < 256; o += 8) {
        float va = 0.f, vb = 0.f;
#pragma unroll
        for (int q = 0; q < 8; q++) {
            float w = convW[(size_t)o*256 + lane + q*32];
            va += ea[lane + q*32] * w;
            vb += eb[lane + q*32] * w;
        }
#pragma unroll
        for (int off = 16; off; off >>= 1) {
            va += __shfl_xor_sync(0xffffffffu, va, off);
            vb += __shfl_xor_sync(0xffffffffu, vb, off);
        }
        if (lane == 0) cat[o] = fmaxf(va, vb) + convb[o];
    }
    if (tid < 256) cat[256 + tid] = ea[tid] - eb[tid];
    __syncthreads();
    for (int o = warp; o < 128; o += 8) {
        float acc = 0.f;
#pragma unroll
        for (int q = 0; q < 16; q++) acc += cat[lane + q*32] * W1[(size_t)o*512 + lane + q*32];
#pragma unroll
        for (int off = 16; off; off >>= 1) acc += __shfl_xor_sync(0xffffffffu, acc, off);
        if (lane == 0) hx[o] = fmaxf(acc + b1[o], 0.f);
    }
    __syncthreads();
    if (warp < 2) {
        float acc = 0.f;
#pragma unroll
        for (int q = 0; q < 4; q++) acc += hx[lane + q*32] * W2[warp*128 + lane + q*32];
#pragma unroll
        for (int off = 16; off; off >>= 1) acc += __shfl_xor_sync(0xffffffffu, acc, off);
        if (lane == 0) lg[warp] = acc + b2[warp];
    }
    __syncthreads();
    if (tid == 0) {
        float l0 = lg[0], l1 = lg[1];
        float m = fmaxf(l0, l1);
        float lse = m + logf(__expf(l0-m) + __expf(l1-m));
        out[bt*2 + 0] = l0 - lse;
        out[bt*2 + 1] = l1 - lse;
    }
}

// ---------------------------------------------------------------------------
extern "C" void kernel_launch(void* const* d_in, const int* in_sizes, int n_in,
                              void* d_out, int out_size)
{
    const float* a      = (const float*)d_in[0];
    const float* bio_a  = (const float*)d_in[1];
    const int*   Aadj   = (const int*)  d_in[2];
    const float* b      = (const float*)d_in[3];
    const float* bio_b  = (const float*)d_in[4];
    const int*   Badj   = (const int*)  d_in[5];
    const float* initW  = (const float*)d_in[6];
    const float* initb  = (const float*)d_in[7];
    const float* projW  = (const float*)d_in[8];
    const float* attw   = (const float*)d_in[9];
    const float* attb   = (const float*)d_in[10];
    const float* ggeW1  = (const float*)d_in[11];
    const float* ggeb1  = (const float*)d_in[12];
    const float* ggeW2  = (const float*)d_in[13];
    const float* ggeb2  = (const float*)d_in[14];
    const float* convW  = (const float*)d_in[15];
    const float* convb  = (const float*)d_in[16];
    const float* ledW1  = (const float*)d_in[17];
    const float* ledb1  = (const float*)d_in[18];
    const float* ledW2  = (const float*)d_in[19];
    const float* ledb2  = (const float*)d_in[20];
    float* out = (float*)d_out;

    cudaFuncSetAttribute(gemm_mma, cudaFuncAttributeMaxDynamicSharedMemorySize,
                         GEMM_SM_BYTES);
    cudaFuncSetAttribute(attn_mma, cudaFuncAttributeMaxDynamicSharedMemorySize,
                         ATTN_SM_BYTES);

    // attn 4th: ncu capture window lands on it
    gemm_mma<<<dim3(64, 2), 512, GEMM_SM_BYTES>>>(bio_a, bio_b, initW, initb,
                                                  attw, attb, PIN, 0);
    gemm_mma<<<dim3(64, 2), 512, GEMM_SM_BYTES>>>(nullptr, nullptr, projW, nullptr,
                                                  attw, attb, POUT, 1);
    gge1_kernel<<<16, 256>>>(a, b, ggeW1, ggeb1);
    attn_mma<<<dim3(NN/64, BT, 2), 256, ATTN_SM_BYTES>>>(Aadj, Badj);
    gge2_kernel<<<16, 256>>>(ggeW2, ggeb2);
    gagaA_kernel<<<dim3(2*BT, 8), 256>>>();
    gagaC_kernel<<<dim3(2*BT, 8), 256>>>();
    led_kernel<<<BT, 256>>>(convW, convb, ledW1, ledb1, ledW2, ledb2, out);
}